// round 7
// baseline (speedup 1.0000x reference)
#include <cuda_runtime.h>
#include <cmath>

#define B 64
#define C 32
#define HW 16
#define IMG (C*HW*HW)        // 8192
#define TOT (B*IMG)          // 524288
#define NE 4096
#define NIDX 21824
#define ROWLEN 341
#define TCODES 128

// dynamic smem for recon_conv: s_in(8192) + s_tmp(4096) + s_w(2304) + red(128) floats + s_code(256) ints
#define SMEM_RC ((8192 + 4096 + 2304 + 128) * 4 + 256 * 4)

// ---------------- scratch (no allocations allowed) ----------------
__device__ float g_zres[TOT];
__device__ float g_zhat[TOT];
__device__ float g_r[TOT];            // only scales 0..2 use this now
__device__ float g_hesq[NE];          // 0.5*||e||^2
__device__ unsigned long long g_res64[NIDX];
__device__ float g_losspart[5*256];
__device__ int   g_itab[4][16][4];
__device__ float g_wtab[4][16][4];

// ---------------- helpers ----------------
__device__ __forceinline__ float cubicw(float x){
    const float A = -0.75f;
    x = fabsf(x);
    if (x <= 1.f) return ((A + 2.f)*x - (A + 3.f))*x*x + 1.f;
    if (x < 2.f)  return A*(((x - 5.f)*x + 8.f)*x - 4.f);
    return 0.f;
}
__device__ __forceinline__ void ffma2(unsigned long long &d, unsigned long long a, unsigned long long b){
    asm("fma.rn.f32x2 %0, %1, %2, %0;" : "+l"(d) : "l"(a), "l"(b));
}
__device__ __forceinline__ unsigned long long pk2(float a, float b){
    return ((unsigned long long)__float_as_uint(b) << 32) | (unsigned long long)__float_as_uint(a);
}
__device__ __forceinline__ float lo2(unsigned long long v){ return __uint_as_float((unsigned)v); }
__device__ __forceinline__ float hi2(unsigned long long v){ return __uint_as_float((unsigned)(v >> 32)); }
__device__ __forceinline__ unsigned ford(float f){
    unsigned u = __float_as_uint(f);
    return (u & 0x80000000u) ? ~u : (u | 0x80000000u);
}

// ---------------- setup ----------------
__global__ void setup_kernel(const float* __restrict__ z, const float* __restrict__ emb){
    int t = blockIdx.x*blockDim.x + threadIdx.x;
    if (t < TOT){ g_zres[t] = z[t]; g_zhat[t] = 0.f; }
    if (t < NIDX) g_res64[t] = 0xFFFFFFFFFFFFFFFFull;
    if (t < NE){
        float s = 0.f;
        #pragma unroll
        for (int k = 0; k < C; k++){ float e = emb[t*C + k]; s += e*e; }
        g_hesq[t] = 0.5f*s;
    }
    if (t < 256){
        int s = t >> 6, rem = t & 63, Y = rem >> 2, a = rem & 3;
        int ph = 1 << s;
        float scale = (float)ph / 16.f;
        float src = ((float)Y + 0.5f)*scale - 0.5f;
        float i0 = floorf(src);
        float fr = src - i0;
        int off = a - 1;
        int idx = (int)i0 + off;
        idx = min(max(idx, 0), ph - 1);
        g_itab[s][Y][a] = idx;
        g_wtab[s][Y][a] = cubicw(fr - (float)off);
    }
}

// ---------------- area pool to [N][C] channel-last (scales 0..2 only) ----------------
__global__ void pool_kernel(int ph){
    int t = blockIdx.x*blockDim.x + threadIdx.x;
    int N = B*ph*ph;
    if (t >= N*C) return;
    int n = t >> 5, c = t & 31;
    int pp = ph*ph;
    int b = n / pp, rem = n % pp, y = rem / ph, x = rem % ph;
    int f = HW / ph;
    const float* base = g_zres + ((b*C + c)*HW + y*f)*HW + x*f;
    float s = 0.f;
    for (int dy = 0; dy < f; dy++)
        for (int dx = 0; dx < f; dx++)
            s += base[dy*HW + dx];
    g_r[n*C + c] = s * (1.f / (float)(f*f));
}

// ---------------- code search: score = 0.5||e||^2 - r.e, FFMA2 packed ----------------
// fmode: 0 = read g_r; 1 = pool f=1 inline (si=4); 2 = pool f=2 inline (si=3)
__global__ __launch_bounds__(128) void argmin_kernel(const float* __restrict__ emb, int N, int chunk,
                                                     int base, int fmode){
    __shared__ __align__(16) float et[C*TCODES];   // transposed [dim][code]
    __shared__ __align__(16) float hs[TCODES];
    int tid = threadIdx.x;
    int row = blockIdx.x*128 + tid;
    int cbase = blockIdx.y * chunk;
    bool active = row < N;

    unsigned long long nrp[C];       // packed {-r_d, -r_d}
    if (active){
        float r[C];
        if (fmode == 1){
            int bb = row >> 8, rem = row & 255;
            const float* p = g_zres + bb*IMG + rem;
            #pragma unroll
            for (int c = 0; c < C; c++) r[c] = p[c*256];
        } else if (fmode == 2){
            int bb = row >> 6, rem = row & 63;
            int y = rem >> 3, x = rem & 7;
            const float* p = g_zres + bb*IMG + (2*y)*16 + 2*x;
            #pragma unroll
            for (int c = 0; c < C; c++){
                const float* q = p + c*256;
                r[c] = (q[0] + q[1] + q[16] + q[17]) * 0.25f;
            }
        } else {
            const float4* rp = (const float4*)(g_r + row*C);
            #pragma unroll
            for (int k = 0; k < 8; k++){
                float4 v = rp[k];
                r[4*k+0] = v.x; r[4*k+1] = v.y; r[4*k+2] = v.z; r[4*k+3] = v.w;
            }
        }
        #pragma unroll
        for (int c = 0; c < C; c++) nrp[c] = pk2(-r[c], -r[c]);
    }
    float best = 3.4e38f; int bcode = 0;

    for (int tb = 0; tb < chunk; tb += TCODES){
        int code = cbase + tb + tid;
        const float4* src = (const float4*)(emb + code*C);
        __syncthreads();   // prior tile fully consumed
        #pragma unroll
        for (int k = 0; k < 8; k++){
            float4 v = src[k];
            et[(4*k+0)*TCODES + tid] = v.x;
            et[(4*k+1)*TCODES + tid] = v.y;
            et[(4*k+2)*TCODES + tid] = v.z;
            et[(4*k+3)*TCODES + tid] = v.w;
        }
        hs[tid] = g_hesq[code];
        __syncthreads();
        if (active){
            for (int jj = 0; jj < TCODES; jj += 8){
                const ulonglong2* h2 = (const ulonglong2*)(hs + jj);
                ulonglong2 ha = h2[0], hb = h2[1];
                unsigned long long a0 = ha.x, a1 = ha.y, a2 = hb.x, a3 = hb.y;
                #pragma unroll
                for (int d = 0; d < C; d++){
                    const ulonglong2* e2 = (const ulonglong2*)(et + d*TCODES + jj);
                    ulonglong2 ea = e2[0], eb = e2[1];
                    ffma2(a0, nrp[d], ea.x);
                    ffma2(a1, nrp[d], ea.y);
                    ffma2(a2, nrp[d], eb.x);
                    ffma2(a3, nrp[d], eb.y);
                }
                float s[8] = {lo2(a0),hi2(a0),lo2(a1),hi2(a1),lo2(a2),hi2(a2),lo2(a3),hi2(a3)};
                #pragma unroll
                for (int k = 0; k < 8; k++){
                    int cc = cbase + tb + jj + k;
                    if (s[k] < best){ best = s[k]; bcode = cc; }
                }
            }
        }
    }
    if (active){
        unsigned long long key = ((unsigned long long)ford(best) << 32) | (unsigned)bcode;
        atomicMin(&g_res64[base + row], key);
    }
}

// ---------------- fused gather(+bicubic) + Phi conv3x3 + residual update + loss ----------------
__global__ __launch_bounds__(128) void recon_conv_kernel(
        const float* __restrict__ z, const float* __restrict__ emb,
        const float* __restrict__ w, const float* __restrict__ bias,
        int si, int ph, int lph, int base, float* __restrict__ out)
{
    extern __shared__ float smem_dyn[];
    float* s_in  = smem_dyn;                 // 8192 floats: [c][y][x]
    float* s_tmp = smem_dyn + 8192;          // 4096 floats: [c][py][x], py<ph<=8
    float* s_w   = smem_dyn + 8192 + 4096;   // 2304
    float* red   = smem_dyn + 8192 + 4096 + 2304;   // 128
    int*  s_code = (int*)(smem_dyn + 8192 + 4096 + 2304 + 128); // 256

    int b = blockIdx.x, og = blockIdx.y, t = threadIdx.x;
    int pp = ph*ph;

    for (int i = t; i < pp; i += 128)
        s_code[i] = (int)(g_res64[base + b*pp + i] & 0xFFFFFFFFull);
    for (int i = t; i < 8*C*9; i += 128) s_w[i] = w[og*8*C*9 + i];
    __syncthreads();

    if (si == 4){
        for (int idx = t; idx < IMG; idx += 128){
            int px = idx & 255, c = idx >> 8;
            s_in[idx] = emb[s_code[px]*C + c];
        }
    } else {
        // pass1: x-direction bicubic -> s_tmp[c][py][x]
        int n1 = C*ph*16;
        for (int idx = t; idx < n1; idx += 128){
            int x = idx & 15;
            int py = (idx >> 4) & (ph - 1);
            int c = idx >> (4 + lph);
            float acc = 0.f;
            #pragma unroll
            for (int ax = 0; ax < 4; ax++){
                int ix = g_itab[si][x][ax];
                acc += g_wtab[si][x][ax] * emb[s_code[py*ph + ix]*C + c];
            }
            s_tmp[(c*8 + py)*16 + x] = acc;
        }
        __syncthreads();
        // pass2: y-direction bicubic -> s_in[c][y][x]
        for (int idx = t; idx < IMG; idx += 128){
            int x = idx & 15, y = (idx >> 4) & 15, c = idx >> 8;
            float acc = 0.f;
            #pragma unroll
            for (int ay = 0; ay < 4; ay++){
                int iy = g_itab[si][y][ay];
                acc += g_wtab[si][y][ay] * s_tmp[(c*8 + iy)*16 + x];
            }
            s_in[idx] = acc;
        }
    }
    __syncthreads();

    int oc_l = t >> 4;   // 0..7
    int x    = t & 15;
    float acc[HW];
    #pragma unroll
    for (int y = 0; y < HW; y++) acc[y] = 0.f;

    for (int ci = 0; ci < C; ci++){
        #pragma unroll
        for (int kx = 0; kx < 3; kx++){
            int xx = x + kx - 1;
            if (xx < 0 || xx >= HW) continue;   // zero pad
            float w0 = s_w[(oc_l*C + ci)*9 + 0*3 + kx];
            float w1 = s_w[(oc_l*C + ci)*9 + 1*3 + kx];
            float w2 = s_w[(oc_l*C + ci)*9 + 2*3 + kx];
            #pragma unroll
            for (int yy = 0; yy < HW; yy++){
                float v = s_in[(ci*16 + yy)*16 + xx];
                if (yy >= 1)      acc[yy-1] += w2 * v;
                acc[yy] += w1 * v;
                if (yy+1 < HW)    acc[yy+1] += w0 * v;
            }
        }
    }

    int oc = og*8 + oc_l;
    float bval = bias[oc];
    float ls = 0.f;
    int gbase = ((b*C + oc)*HW)*HW + x;
    #pragma unroll
    for (int y = 0; y < HW; y++){
        float qv = 0.5f*s_in[(oc*16 + y)*16 + x] + 0.5f*(acc[y] + bval);
        int g = gbase + y*HW;
        float zh = g_zhat[g] + qv;
        if (si < 4){
            g_zhat[g] = zh;
            g_zres[g] -= qv;
        } else {
            out[g] = zh;   // straight-through value == z_hat
        }
        float d = zh - z[g];
        ls += d*d;
    }
    red[t] = ls;
    __syncthreads();
    for (int s = 64; s > 0; s >>= 1){
        if (t < s) red[t] += red[t+s];
        __syncthreads();
    }
    if (t == 0) g_losspart[si*256 + b*4 + og] = red[0];
}

// ---------------- final pack: loss (parallel reduce) + idx floats ----------------
__global__ void pack_kernel(float* __restrict__ out){
    int t = blockIdx.x*blockDim.x + threadIdx.x;
    if (blockIdx.x == 0){
        __shared__ float red[256];
        float s = 0.f;
        for (int i = threadIdx.x; i < 5*256; i += 256) s += g_losspart[i];
        red[threadIdx.x] = s;
        __syncthreads();
        for (int k = 128; k > 0; k >>= 1){
            if (threadIdx.x < k) red[threadIdx.x] += red[threadIdx.x + k];
            __syncthreads();
        }
        if (threadIdx.x == 0) out[TOT] = red[0] * (1.25f / ((float)TOT * 5.f));
    }
    if (t < NIDX){
        int base, pp, ofs_row;
        if      (t <   64){ base=0;    pp=1;   ofs_row=0;  }
        else if (t <  320){ base=64;   pp=4;   ofs_row=1;  }
        else if (t < 1344){ base=320;  pp=16;  ofs_row=5;  }
        else if (t < 5440){ base=1344; pp=64;  ofs_row=21; }
        else              { base=5440; pp=256; ofs_row=85; }
        int r = t - base;
        int bb = r / pp, p = r % pp;
        int code = (int)(g_res64[t] & 0xFFFFFFFFull);
        out[TOT + 1 + bb*ROWLEN + ofs_row + p] = (float)code;
    }
}

extern "C" void kernel_launch(void* const* d_in, const int* in_sizes, int n_in,
                              void* d_out, int out_size){
    // Bind inputs by element count: z=524288, emb=131072, phi_w=36864, phi_b=128 (all distinct).
    const float* z = 0; const float* emb = 0; const float* phi_w = 0; const float* phi_b = 0;
    for (int i = 0; i < n_in; i++){
        switch (in_sizes[i]){
            case 524288: z     = (const float*)d_in[i]; break;
            case 131072: emb   = (const float*)d_in[i]; break;
            case 36864:  phi_w = (const float*)d_in[i]; break;
            case 128:    phi_b = (const float*)d_in[i]; break;
            default: break;
        }
    }
    float* out = (float*)d_out;
    (void)out_size;

    cudaFuncSetAttribute(recon_conv_kernel, cudaFuncAttributeMaxDynamicSharedMemorySize, SMEM_RC);

    setup_kernel<<<(TOT + 255)/256, 256>>>(z, emb);

    // numpy-exact Phi tick selection (float64 linspace semantics, first-wins argmin)
    double start = 1.0/12.0;
    double stop  = 1.0 - 1.0/12.0;
    double step  = (stop - start) / 3.0;
    double ticks[4];
    for (int i = 0; i < 4; i++) ticks[i] = (double)i * step + start;
    ticks[3] = stop;
    int pis[5];
    for (int si = 0; si < 5; si++){
        double target = (double)si / 4.0;
        int bestp = 0; double bestd = fabs(ticks[0] - target);
        for (int p = 1; p < 4; p++){
            double d = fabs(ticks[p] - target);
            if (d < bestd){ bestd = d; bestp = p; }
        }
        pis[si] = bestp;
    }

    const int scales[5] = {1, 2, 4, 8, 16};
    const int splits[5] = {32, 32, 16, 8, 4};
    const int iofs[5]   = {0, 64, 320, 1344, 5440};

    for (int si = 0; si < 5; si++){
        int ph = scales[si];
        int N  = B*ph*ph;
        if (si < 3) pool_kernel<<<(N*C + 255)/256, 256>>>(ph);
        int fmode = (si == 4) ? 1 : (si == 3 ? 2 : 0);
        dim3 g((N + 127)/128, splits[si]);
        argmin_kernel<<<g, 128>>>(emb, N, NE/splits[si], iofs[si], fmode);
        recon_conv_kernel<<<dim3(B, 4), 128, SMEM_RC>>>(
            z, emb, phi_w + pis[si]*C*C*9, phi_b + pis[si]*C,
            si, ph, si, iofs[si], (si == 4) ? out : (float*)0);
    }
    pack_kernel<<<(NIDX + 255)/256, 256>>>(out);
}

// round 8
// speedup vs baseline: 1.5144x; 1.5144x over previous
#include <cuda_runtime.h>
#include <cmath>

#define B 64
#define C 32
#define HW 16
#define IMG (C*HW*HW)        // 8192
#define TOT (B*IMG)          // 524288
#define NE 4096
#define NIDX 21824
#define ROWLEN 341
#define TCODES 128

// ---------------- scratch (no allocations allowed) ----------------
__device__ float g_zres[TOT];
__device__ float g_zhat[TOT];
__device__ float g_r[TOT];            // only scales 0..2 use this
__device__ float g_qup[TOT];
__device__ float g_hesq[NE];          // 0.5*||e||^2
__device__ unsigned long long g_res64[NIDX];
__device__ float g_losspart[5*256];
__device__ int   g_itab[4][16][4];
__device__ float g_wtab[4][16][4];

// ---------------- helpers ----------------
__device__ __forceinline__ float cubicw(float x){
    const float A = -0.75f;
    x = fabsf(x);
    if (x <= 1.f) return ((A + 2.f)*x - (A + 3.f))*x*x + 1.f;
    if (x < 2.f)  return A*(((x - 5.f)*x + 8.f)*x - 4.f);
    return 0.f;
}
__device__ __forceinline__ void ffma2(unsigned long long &d, unsigned long long a, unsigned long long b){
    asm("fma.rn.f32x2 %0, %1, %2, %0;" : "+l"(d) : "l"(a), "l"(b));
}
__device__ __forceinline__ unsigned long long pk2(float a, float b){
    return ((unsigned long long)__float_as_uint(b) << 32) | (unsigned long long)__float_as_uint(a);
}
__device__ __forceinline__ float lo2(unsigned long long v){ return __uint_as_float((unsigned)v); }
__device__ __forceinline__ float hi2(unsigned long long v){ return __uint_as_float((unsigned)(v >> 32)); }
__device__ __forceinline__ unsigned ford(float f){
    unsigned u = __float_as_uint(f);
    return (u & 0x80000000u) ? ~u : (u | 0x80000000u);
}

// ---------------- setup ----------------
__global__ void setup_kernel(const float* __restrict__ z, const float* __restrict__ emb){
    int t = blockIdx.x*blockDim.x + threadIdx.x;
    if (t < TOT){ g_zres[t] = z[t]; g_zhat[t] = 0.f; }
    if (t < NIDX) g_res64[t] = 0xFFFFFFFFFFFFFFFFull;
    if (t < NE){
        float s = 0.f;
        #pragma unroll
        for (int k = 0; k < C; k++){ float e = emb[t*C + k]; s += e*e; }
        g_hesq[t] = 0.5f*s;
    }
    if (t < 256){
        int s = t >> 6, rem = t & 63, Y = rem >> 2, a = rem & 3;
        int ph = 1 << s;
        float scale = (float)ph / 16.f;
        float src = ((float)Y + 0.5f)*scale - 0.5f;
        float i0 = floorf(src);
        float fr = src - i0;
        int off = a - 1;
        int idx = (int)i0 + off;
        idx = min(max(idx, 0), ph - 1);
        g_itab[s][Y][a] = idx;
        g_wtab[s][Y][a] = cubicw(fr - (float)off);
    }
}

// ---------------- area pool to [N][C] channel-last (scales 0..2 only) ----------------
__global__ void pool_kernel(int ph){
    int t = blockIdx.x*blockDim.x + threadIdx.x;
    int N = B*ph*ph;
    if (t >= N*C) return;
    int n = t >> 5, c = t & 31;
    int pp = ph*ph;
    int b = n / pp, rem = n % pp, y = rem / ph, x = rem % ph;
    int f = HW / ph;
    const float* base = g_zres + ((b*C + c)*HW + y*f)*HW + x*f;
    float s = 0.f;
    for (int dy = 0; dy < f; dy++)
        for (int dx = 0; dx < f; dx++)
            s += base[dy*HW + dx];
    g_r[n*C + c] = s * (1.f / (float)(f*f));
}

// ---------------- code search: score = 0.5||e||^2 - r.e, FFMA2 packed ----------------
// fmode: 0 = read g_r; 1 = pool f=1 inline (si=4); 2 = pool f=2 inline (si=3)
__global__ __launch_bounds__(128) void argmin_kernel(const float* __restrict__ emb, int N, int chunk,
                                                     int base, int fmode){
    __shared__ __align__(16) float et[C*TCODES];   // transposed [dim][code]
    __shared__ __align__(16) float hs[TCODES];
    int tid = threadIdx.x;
    int row = blockIdx.x*128 + tid;
    int cbase = blockIdx.y * chunk;
    bool active = row < N;

    unsigned long long nrp[C];       // packed {-r_d, -r_d}
    if (active){
        float r[C];
        if (fmode == 1){
            int bb = row >> 8, rem = row & 255;
            const float* p = g_zres + bb*IMG + rem;
            #pragma unroll
            for (int c = 0; c < C; c++) r[c] = p[c*256];
        } else if (fmode == 2){
            int bb = row >> 6, rem = row & 63;
            int y = rem >> 3, x = rem & 7;
            const float* p = g_zres + bb*IMG + (2*y)*16 + 2*x;
            #pragma unroll
            for (int c = 0; c < C; c++){
                const float* q = p + c*256;
                r[c] = (q[0] + q[1] + q[16] + q[17]) * 0.25f;
            }
        } else {
            const float4* rp = (const float4*)(g_r + row*C);
            #pragma unroll
            for (int k = 0; k < 8; k++){
                float4 v = rp[k];
                r[4*k+0] = v.x; r[4*k+1] = v.y; r[4*k+2] = v.z; r[4*k+3] = v.w;
            }
        }
        #pragma unroll
        for (int c = 0; c < C; c++) nrp[c] = pk2(-r[c], -r[c]);
    }
    float best = 3.4e38f; int bcode = 0;

    for (int tb = 0; tb < chunk; tb += TCODES){
        int code = cbase + tb + tid;
        const float4* src = (const float4*)(emb + code*C);
        __syncthreads();   // prior tile fully consumed
        #pragma unroll
        for (int k = 0; k < 8; k++){
            float4 v = src[k];
            et[(4*k+0)*TCODES + tid] = v.x;
            et[(4*k+1)*TCODES + tid] = v.y;
            et[(4*k+2)*TCODES + tid] = v.z;
            et[(4*k+3)*TCODES + tid] = v.w;
        }
        hs[tid] = g_hesq[code];
        __syncthreads();
        if (active){
            for (int jj = 0; jj < TCODES; jj += 8){
                const ulonglong2* h2 = (const ulonglong2*)(hs + jj);
                ulonglong2 ha = h2[0], hb = h2[1];
                unsigned long long a0 = ha.x, a1 = ha.y, a2 = hb.x, a3 = hb.y;
                #pragma unroll
                for (int d = 0; d < C; d++){
                    const ulonglong2* e2 = (const ulonglong2*)(et + d*TCODES + jj);
                    ulonglong2 ea = e2[0], eb = e2[1];
                    ffma2(a0, nrp[d], ea.x);
                    ffma2(a1, nrp[d], ea.y);
                    ffma2(a2, nrp[d], eb.x);
                    ffma2(a3, nrp[d], eb.y);
                }
                float s[8] = {lo2(a0),hi2(a0),lo2(a1),hi2(a1),lo2(a2),hi2(a2),lo2(a3),hi2(a3)};
                #pragma unroll
                for (int k = 0; k < 8; k++){
                    int cc = cbase + tb + jj + k;
                    if (s[k] < best){ best = s[k]; bcode = cc; }
                }
            }
        }
    }
    if (active){
        unsigned long long key = ((unsigned long long)ford(best) << 32) | (unsigned)bcode;
        atomicMin(&g_res64[base + row], key);
    }
}

// ---------------- gather + bicubic upsample to q_up [B][C][16][16] ----------------
__global__ void gather_kernel(const float* __restrict__ emb, int si, int ph, int base){
    int t = blockIdx.x*blockDim.x + threadIdx.x;
    if (t >= TOT) return;
    int x = t & 15, y = (t >> 4) & 15, c = (t >> 8) & 31, b = t >> 13;
    float out;
    if (si == 4){
        int n = (b*16 + y)*16 + x;
        int code = (int)(g_res64[base + n] & 0xFFFFFFFFull);
        out = emb[code*C + c];
    } else {
        int pp = ph*ph;
        float acc = 0.f;
        #pragma unroll
        for (int ax = 0; ax < 4; ax++){
            int   ix = g_itab[si][x][ax];
            float wx = g_wtab[si][x][ax];
            float sy = 0.f;
            #pragma unroll
            for (int ay = 0; ay < 4; ay++){
                int   iy = g_itab[si][y][ay];
                float wy = g_wtab[si][y][ay];
                int n = b*pp + iy*ph + ix;
                int code = (int)(g_res64[base + n] & 0xFFFFFFFFull);
                sy += wy * emb[code*C + c];
            }
            acc += wx * sy;
        }
        out = acc;
    }
    g_qup[t] = out;
}

// ---------------- Phi conv3x3 + residual update + loss (512 thr: oc8 x x16 x yq4) ----------------
__global__ __launch_bounds__(512) void conv_update_kernel(const float* __restrict__ z,
        const float* __restrict__ w, const float* __restrict__ bias, int si, float* __restrict__ out){
    __shared__ float s_in[C][HW][HW];   // 32 KB
    __shared__ float s_w[8*C*9];        // 9 KB
    __shared__ float red[512];          // 2 KB
    int b = blockIdx.x, og = blockIdx.y, t = threadIdx.x;

    const float4* gsrc = (const float4*)(g_qup + b*IMG);
    float4* sdst = (float4*)&s_in[0][0][0];
    for (int i = t; i < IMG/4; i += 512) sdst[i] = gsrc[i];
    for (int i = t; i < 8*C*9; i += 512) s_w[i] = w[og*8*C*9 + i];
    __syncthreads();

    int x    = t & 15;        // lane dimension -> conflict-free SMEM
    int yq   = (t >> 4) & 3;  // y-quarter: rows 4yq..4yq+3
    int oc_l = t >> 6;        // 0..7
    int y0 = 4*yq;

    float acc0 = 0.f, acc1 = 0.f, acc2 = 0.f, acc3 = 0.f;

    for (int ci = 0; ci < C; ci++){
        #pragma unroll
        for (int kx = 0; kx < 3; kx++){
            int xx = x + kx - 1;
            if (xx < 0 || xx >= HW) continue;   // zero pad
            const float* wp = s_w + (oc_l*C + ci)*9 + kx;
            float w0 = wp[0], w1 = wp[3], w2 = wp[6];
            // rows y0-1 .. y0+4
            float v0 = (y0 >= 1)      ? s_in[ci][y0-1][xx] : 0.f;
            float v1 = s_in[ci][y0+0][xx];
            float v2 = s_in[ci][y0+1][xx];
            float v3 = s_in[ci][y0+2][xx];
            float v4 = s_in[ci][y0+3][xx];
            float v5 = (y0 + 4 < HW)  ? s_in[ci][y0+4][xx] : 0.f;
            // out[y] = sum_ky w[ky]*in[y+ky-1]
            acc0 += w0*v0 + w1*v1 + w2*v2;
            acc1 += w0*v1 + w1*v2 + w2*v3;
            acc2 += w0*v2 + w1*v3 + w2*v4;
            acc3 += w0*v3 + w1*v4 + w2*v5;
        }
    }

    int oc = og*8 + oc_l;
    float bval = bias[oc];
    float ls = 0.f;
    int gbase = ((b*C + oc)*HW)*HW + x;
    float accs[4] = {acc0, acc1, acc2, acc3};
    #pragma unroll
    for (int i = 0; i < 4; i++){
        int y = y0 + i;
        float qv = 0.5f*s_in[oc][y][x] + 0.5f*(accs[i] + bval);
        int g = gbase + y*HW;
        float zh = g_zhat[g] + qv;
        if (si < 4){
            g_zhat[g] = zh;
            g_zres[g] -= qv;
        } else {
            out[g] = zh;   // straight-through value == z_hat
        }
        float d = zh - z[g];
        ls += d*d;
    }
    red[t] = ls;
    __syncthreads();
    for (int s = 256; s > 0; s >>= 1){
        if (t < s) red[t] += red[t+s];
        __syncthreads();
    }
    if (t == 0) g_losspart[si*256 + b*4 + og] = red[0];
}

// ---------------- final pack: loss (parallel reduce) + idx floats ----------------
__global__ void pack_kernel(float* __restrict__ out){
    int t = blockIdx.x*blockDim.x + threadIdx.x;
    if (blockIdx.x == 0){
        __shared__ float red[256];
        float s = 0.f;
        for (int i = threadIdx.x; i < 5*256; i += 256) s += g_losspart[i];
        red[threadIdx.x] = s;
        __syncthreads();
        for (int k = 128; k > 0; k >>= 1){
            if (threadIdx.x < k) red[threadIdx.x] += red[threadIdx.x + k];
            __syncthreads();
        }
        if (threadIdx.x == 0) out[TOT] = red[0] * (1.25f / ((float)TOT * 5.f));
    }
    if (t < NIDX){
        int base, pp, ofs_row;
        if      (t <   64){ base=0;    pp=1;   ofs_row=0;  }
        else if (t <  320){ base=64;   pp=4;   ofs_row=1;  }
        else if (t < 1344){ base=320;  pp=16;  ofs_row=5;  }
        else if (t < 5440){ base=1344; pp=64;  ofs_row=21; }
        else              { base=5440; pp=256; ofs_row=85; }
        int r = t - base;
        int bb = r / pp, p = r % pp;
        int code = (int)(g_res64[t] & 0xFFFFFFFFull);
        out[TOT + 1 + bb*ROWLEN + ofs_row + p] = (float)code;
    }
}

extern "C" void kernel_launch(void* const* d_in, const int* in_sizes, int n_in,
                              void* d_out, int out_size){
    // Bind inputs by element count: z=524288, emb=131072, phi_w=36864, phi_b=128 (all distinct).
    const float* z = 0; const float* emb = 0; const float* phi_w = 0; const float* phi_b = 0;
    for (int i = 0; i < n_in; i++){
        switch (in_sizes[i]){
            case 524288: z     = (const float*)d_in[i]; break;
            case 131072: emb   = (const float*)d_in[i]; break;
            case 36864:  phi_w = (const float*)d_in[i]; break;
            case 128:    phi_b = (const float*)d_in[i]; break;
            default: break;
        }
    }
    float* out = (float*)d_out;
    (void)out_size;

    setup_kernel<<<(TOT + 255)/256, 256>>>(z, emb);

    // numpy-exact Phi tick selection (float64 linspace semantics, first-wins argmin)
    double start = 1.0/12.0;
    double stop  = 1.0 - 1.0/12.0;
    double step  = (stop - start) / 3.0;
    double ticks[4];
    for (int i = 0; i < 4; i++) ticks[i] = (double)i * step + start;
    ticks[3] = stop;
    int pis[5];
    for (int si = 0; si < 5; si++){
        double target = (double)si / 4.0;
        int bestp = 0; double bestd = fabs(ticks[0] - target);
        for (int p = 1; p < 4; p++){
            double d = fabs(ticks[p] - target);
            if (d < bestd){ bestd = d; bestp = p; }
        }
        pis[si] = bestp;
    }

    const int scales[5] = {1, 2, 4, 8, 16};
    const int splits[5] = {32, 32, 16, 8, 4};
    const int iofs[5]   = {0, 64, 320, 1344, 5440};

    for (int si = 0; si < 5; si++){
        int ph = scales[si];
        int N  = B*ph*ph;
        if (si < 3) pool_kernel<<<(N*C + 255)/256, 256>>>(ph);
        int fmode = (si == 4) ? 1 : (si == 3 ? 2 : 0);
        dim3 g((N + 127)/128, splits[si]);
        argmin_kernel<<<g, 128>>>(emb, N, NE/splits[si], iofs[si], fmode);
        gather_kernel<<<(TOT + 255)/256, 256>>>(emb, si, ph, iofs[si]);
        conv_update_kernel<<<dim3(B, 4), 512>>>(z, phi_w + pis[si]*C*C*9, phi_b + pis[si]*C,
                                                si, (si == 4) ? out : (float*)0);
    }
    pack_kernel<<<(NIDX + 255)/256, 256>>>(out);
}

// round 9
// speedup vs baseline: 1.6702x; 1.1028x over previous
#include <cuda_runtime.h>
#include <cmath>

#define B 64
#define C 32
#define HW 16
#define IMG (C*HW*HW)        // 8192
#define TOT (B*IMG)          // 524288
#define NE 4096
#define NIDX 21824
#define ROWLEN 341
#define TCODES 128

// ---------------- scratch (no allocations allowed) ----------------
__device__ float g_zres[TOT];
__device__ float g_zhat[TOT];
__device__ float g_r[TOT];            // only scales 0..1 use this
__device__ float g_qup[TOT];
__device__ float g_hesq[NE];          // 0.5*||e||^2
__device__ unsigned long long g_res64[NIDX];
__device__ float g_losspart[5*256];
__device__ int   g_itab[4][16][4];
__device__ float g_wtab[4][16][4];

// ---------------- helpers ----------------
__device__ __forceinline__ float cubicw(float x){
    const float A = -0.75f;
    x = fabsf(x);
    if (x <= 1.f) return ((A + 2.f)*x - (A + 3.f))*x*x + 1.f;
    if (x < 2.f)  return A*(((x - 5.f)*x + 8.f)*x - 4.f);
    return 0.f;
}
__device__ __forceinline__ void ffma2(unsigned long long &d, unsigned long long a, unsigned long long b){
    asm("fma.rn.f32x2 %0, %1, %2, %0;" : "+l"(d) : "l"(a), "l"(b));
}
__device__ __forceinline__ unsigned long long pk2(float a, float b){
    return ((unsigned long long)__float_as_uint(b) << 32) | (unsigned long long)__float_as_uint(a);
}
__device__ __forceinline__ float lo2(unsigned long long v){ return __uint_as_float((unsigned)v); }
__device__ __forceinline__ float hi2(unsigned long long v){ return __uint_as_float((unsigned)(v >> 32)); }
__device__ __forceinline__ unsigned ford(float f){
    unsigned u = __float_as_uint(f);
    return (u & 0x80000000u) ? ~u : (u | 0x80000000u);
}

// pooled residual row loader. fmode: 0 = g_r, 1 = f=1, 2 = f=2, 3 = f=4
__device__ __forceinline__ void load_r(int row, int fmode, float* r){
    if (fmode == 1){
        int bb = row >> 8, rem = row & 255;
        const float* p = g_zres + bb*IMG + rem;
        #pragma unroll
        for (int c = 0; c < C; c++) r[c] = p[c*256];
    } else if (fmode == 2){
        int bb = row >> 6, rem = row & 63;
        int y = rem >> 3, x = rem & 7;
        const float* p = g_zres + bb*IMG + (2*y)*16 + 2*x;
        #pragma unroll
        for (int c = 0; c < C; c++){
            const float* q = p + c*256;
            r[c] = (q[0] + q[1] + q[16] + q[17]) * 0.25f;
        }
    } else if (fmode == 3){
        int bb = row >> 4, rem = row & 15;
        int y = rem >> 2, x = rem & 3;
        const float* p = g_zres + bb*IMG + (4*y)*16 + 4*x;
        #pragma unroll
        for (int c = 0; c < C; c++){
            const float* q = p + c*256;
            float s = 0.f;
            #pragma unroll
            for (int dy = 0; dy < 4; dy++){
                s += q[dy*16 + 0]; s += q[dy*16 + 1]; s += q[dy*16 + 2]; s += q[dy*16 + 3];
            }
            r[c] = s * 0.0625f;
        }
    } else {
        const float4* rp = (const float4*)(g_r + row*C);
        #pragma unroll
        for (int k = 0; k < 8; k++){
            float4 v = rp[k];
            r[4*k+0] = v.x; r[4*k+1] = v.y; r[4*k+2] = v.z; r[4*k+3] = v.w;
        }
    }
}

// ---------------- setup ----------------
__global__ void setup_kernel(const float* __restrict__ z, const float* __restrict__ emb){
    int t = blockIdx.x*blockDim.x + threadIdx.x;
    if (t < TOT){ g_zres[t] = z[t]; g_zhat[t] = 0.f; }
    if (t < NIDX) g_res64[t] = 0xFFFFFFFFFFFFFFFFull;
    if (t < NE){
        float s = 0.f;
        #pragma unroll
        for (int k = 0; k < C; k++){ float e = emb[t*C + k]; s += e*e; }
        g_hesq[t] = 0.5f*s;
    }
    if (t < 256){
        int s = t >> 6, rem = t & 63, Y = rem >> 2, a = rem & 3;
        int ph = 1 << s;
        float scale = (float)ph / 16.f;
        float src = ((float)Y + 0.5f)*scale - 0.5f;
        float i0 = floorf(src);
        float fr = src - i0;
        int off = a - 1;
        int idx = (int)i0 + off;
        idx = min(max(idx, 0), ph - 1);
        g_itab[s][Y][a] = idx;
        g_wtab[s][Y][a] = cubicw(fr - (float)off);
    }
}

// ---------------- area pool to [N][C] channel-last (scales 0..1 only) ----------------
__global__ void pool_kernel(int ph){
    int t = blockIdx.x*blockDim.x + threadIdx.x;
    int N = B*ph*ph;
    if (t >= N*C) return;
    int n = t >> 5, c = t & 31;
    int pp = ph*ph;
    int b = n / pp, rem = n % pp, y = rem / ph, x = rem % ph;
    int f = HW / ph;
    const float* base = g_zres + ((b*C + c)*HW + y*f)*HW + x*f;
    float s = 0.f;
    for (int dy = 0; dy < f; dy++)
        for (int dx = 0; dx < f; dx++)
            s += base[dy*HW + dx];
    g_r[n*C + c] = s * (1.f / (float)(f*f));
}

// ---------------- code search: score = 0.5||e||^2 - r.e, FFMA2, TROWS rows/thread ----------------
template<int TROWS>
__global__ __launch_bounds__(128) void argmin_kernel(const float* __restrict__ emb, int N, int chunk,
                                                     int base, int fmode){
    __shared__ __align__(16) float et[C*TCODES];   // transposed [dim][code]
    __shared__ __align__(16) float hs[TCODES];
    int tid = threadIdx.x;
    int row0 = blockIdx.x*(128*TROWS) + tid;
    int cbase = blockIdx.y * chunk;

    unsigned long long nrp[TROWS][C];    // packed {-r_d, -r_d}
    bool act[TROWS];
    #pragma unroll
    for (int tr = 0; tr < TROWS; tr++){
        int row = row0 + tr*128;
        act[tr] = row < N;
        if (act[tr]){
            float r[C];
            load_r(row, fmode, r);
            #pragma unroll
            for (int c = 0; c < C; c++) nrp[tr][c] = pk2(-r[c], -r[c]);
        }
    }
    float best[TROWS]; int bcode[TROWS];
    #pragma unroll
    for (int tr = 0; tr < TROWS; tr++){ best[tr] = 3.4e38f; bcode[tr] = 0; }

    for (int tb = 0; tb < chunk; tb += TCODES){
        int code = cbase + tb + tid;
        const float4* src = (const float4*)(emb + code*C);
        __syncthreads();   // prior tile fully consumed
        #pragma unroll
        for (int k = 0; k < 8; k++){
            float4 v = src[k];
            et[(4*k+0)*TCODES + tid] = v.x;
            et[(4*k+1)*TCODES + tid] = v.y;
            et[(4*k+2)*TCODES + tid] = v.z;
            et[(4*k+3)*TCODES + tid] = v.w;
        }
        hs[tid] = g_hesq[code];
        __syncthreads();

        for (int jj = 0; jj < TCODES; jj += 8){
            const ulonglong2* h2 = (const ulonglong2*)(hs + jj);
            ulonglong2 ha = h2[0], hb = h2[1];
            unsigned long long acc[TROWS][4];
            #pragma unroll
            for (int tr = 0; tr < TROWS; tr++){
                acc[tr][0] = ha.x; acc[tr][1] = ha.y; acc[tr][2] = hb.x; acc[tr][3] = hb.y;
            }
            #pragma unroll
            for (int d = 0; d < C; d++){
                const ulonglong2* e2 = (const ulonglong2*)(et + d*TCODES + jj);
                ulonglong2 ea = e2[0], eb = e2[1];
                #pragma unroll
                for (int tr = 0; tr < TROWS; tr++){
                    ffma2(acc[tr][0], nrp[tr][d], ea.x);
                    ffma2(acc[tr][1], nrp[tr][d], ea.y);
                    ffma2(acc[tr][2], nrp[tr][d], eb.x);
                    ffma2(acc[tr][3], nrp[tr][d], eb.y);
                }
            }
            #pragma unroll
            for (int tr = 0; tr < TROWS; tr++){
                float s[8] = {lo2(acc[tr][0]),hi2(acc[tr][0]),lo2(acc[tr][1]),hi2(acc[tr][1]),
                              lo2(acc[tr][2]),hi2(acc[tr][2]),lo2(acc[tr][3]),hi2(acc[tr][3])};
                #pragma unroll
                for (int k = 0; k < 8; k++){
                    int cc = cbase + tb + jj + k;
                    if (s[k] < best[tr]){ best[tr] = s[k]; bcode[tr] = cc; }
                }
            }
        }
    }
    #pragma unroll
    for (int tr = 0; tr < TROWS; tr++){
        if (act[tr]){
            unsigned long long key = ((unsigned long long)ford(best[tr]) << 32) | (unsigned)bcode[tr];
            atomicMin(&g_res64[base + row0 + tr*128], key);
        }
    }
}

// ---------------- gather + bicubic upsample to q_up [B][C][16][16] ----------------
__global__ void gather_kernel(const float* __restrict__ emb, int si, int ph, int base){
    int t = blockIdx.x*blockDim.x + threadIdx.x;
    if (t >= TOT) return;
    int x = t & 15, y = (t >> 4) & 15, c = (t >> 8) & 31, b = t >> 13;
    float out;
    if (si == 4){
        int n = (b*16 + y)*16 + x;
        int code = (int)(g_res64[base + n] & 0xFFFFFFFFull);
        out = emb[code*C + c];
    } else {
        int pp = ph*ph;
        float acc = 0.f;
        #pragma unroll
        for (int ax = 0; ax < 4; ax++){
            int   ix = g_itab[si][x][ax];
            float wx = g_wtab[si][x][ax];
            float sy = 0.f;
            #pragma unroll
            for (int ay = 0; ay < 4; ay++){
                int   iy = g_itab[si][y][ay];
                float wy = g_wtab[si][y][ay];
                int n = b*pp + iy*ph + ix;
                int code = (int)(g_res64[base + n] & 0xFFFFFFFFull);
                sy += wy * emb[code*C + c];
            }
            acc += wx * sy;
        }
        out = acc;
    }
    g_qup[t] = out;
}

// ---------------- Phi conv3x3 + residual update + loss (512 thr: oc8 x x16 x yq4) ----------------
__global__ __launch_bounds__(512) void conv_update_kernel(const float* __restrict__ z,
        const float* __restrict__ w, const float* __restrict__ bias, int si, float* __restrict__ out){
    __shared__ float s_in[C][HW][HW];   // 32 KB
    __shared__ float s_w[8*C*9];        // 9 KB
    __shared__ float red[512];          // 2 KB
    int b = blockIdx.x, og = blockIdx.y, t = threadIdx.x;

    const float4* gsrc = (const float4*)(g_qup + b*IMG);
    float4* sdst = (float4*)&s_in[0][0][0];
    for (int i = t; i < IMG/4; i += 512) sdst[i] = gsrc[i];
    for (int i = t; i < 8*C*9; i += 512) s_w[i] = w[og*8*C*9 + i];
    __syncthreads();

    int x    = t & 15;        // lane dimension -> conflict-free SMEM
    int yq   = (t >> 4) & 3;  // y-quarter: rows 4yq..4yq+3
    int oc_l = t >> 6;        // 0..7
    int y0 = 4*yq;

    float acc0 = 0.f, acc1 = 0.f, acc2 = 0.f, acc3 = 0.f;

    for (int ci = 0; ci < C; ci++){
        #pragma unroll
        for (int kx = 0; kx < 3; kx++){
            int xx = x + kx - 1;
            if (xx < 0 || xx >= HW) continue;   // zero pad
            const float* wp = s_w + (oc_l*C + ci)*9 + kx;
            float w0 = wp[0], w1 = wp[3], w2 = wp[6];
            float v0 = (y0 >= 1)      ? s_in[ci][y0-1][xx] : 0.f;
            float v1 = s_in[ci][y0+0][xx];
            float v2 = s_in[ci][y0+1][xx];
            float v3 = s_in[ci][y0+2][xx];
            float v4 = s_in[ci][y0+3][xx];
            float v5 = (y0 + 4 < HW)  ? s_in[ci][y0+4][xx] : 0.f;
            acc0 += w0*v0 + w1*v1 + w2*v2;
            acc1 += w0*v1 + w1*v2 + w2*v3;
            acc2 += w0*v2 + w1*v3 + w2*v4;
            acc3 += w0*v3 + w1*v4 + w2*v5;
        }
    }

    int oc = og*8 + oc_l;
    float bval = bias[oc];
    float ls = 0.f;
    int gbase = ((b*C + oc)*HW)*HW + x;
    float accs[4] = {acc0, acc1, acc2, acc3};
    #pragma unroll
    for (int i = 0; i < 4; i++){
        int y = y0 + i;
        float qv = 0.5f*s_in[oc][y][x] + 0.5f*(accs[i] + bval);
        int g = gbase + y*HW;
        float zh = g_zhat[g] + qv;
        if (si < 4){
            g_zhat[g] = zh;
            g_zres[g] -= qv;
        } else {
            out[g] = zh;   // straight-through value == z_hat
        }
        float d = zh - z[g];
        ls += d*d;
    }
    red[t] = ls;
    __syncthreads();
    for (int s = 256; s > 0; s >>= 1){
        if (t < s) red[t] += red[t+s];
        __syncthreads();
    }
    if (t == 0) g_losspart[si*256 + b*4 + og] = red[0];
}

// ---------------- final pack: loss (parallel reduce) + idx floats ----------------
__global__ void pack_kernel(float* __restrict__ out){
    int t = blockIdx.x*blockDim.x + threadIdx.x;
    if (blockIdx.x == 0){
        __shared__ float red[256];
        float s = 0.f;
        for (int i = threadIdx.x; i < 5*256; i += 256) s += g_losspart[i];
        red[threadIdx.x] = s;
        __syncthreads();
        for (int k = 128; k > 0; k >>= 1){
            if (threadIdx.x < k) red[threadIdx.x] += red[threadIdx.x + k];
            __syncthreads();
        }
        if (threadIdx.x == 0) out[TOT] = red[0] * (1.25f / ((float)TOT * 5.f));
    }
    if (t < NIDX){
        int base, pp, ofs_row;
        if      (t <   64){ base=0;    pp=1;   ofs_row=0;  }
        else if (t <  320){ base=64;   pp=4;   ofs_row=1;  }
        else if (t < 1344){ base=320;  pp=16;  ofs_row=5;  }
        else if (t < 5440){ base=1344; pp=64;  ofs_row=21; }
        else              { base=5440; pp=256; ofs_row=85; }
        int r = t - base;
        int bb = r / pp, p = r % pp;
        int code = (int)(g_res64[t] & 0xFFFFFFFFull);
        out[TOT + 1 + bb*ROWLEN + ofs_row + p] = (float)code;
    }
}

extern "C" void kernel_launch(void* const* d_in, const int* in_sizes, int n_in,
                              void* d_out, int out_size){
    // Bind inputs by element count: z=524288, emb=131072, phi_w=36864, phi_b=128 (all distinct).
    const float* z = 0; const float* emb = 0; const float* phi_w = 0; const float* phi_b = 0;
    for (int i = 0; i < n_in; i++){
        switch (in_sizes[i]){
            case 524288: z     = (const float*)d_in[i]; break;
            case 131072: emb   = (const float*)d_in[i]; break;
            case 36864:  phi_w = (const float*)d_in[i]; break;
            case 128:    phi_b = (const float*)d_in[i]; break;
            default: break;
        }
    }
    float* out = (float*)d_out;
    (void)out_size;

    setup_kernel<<<(TOT + 255)/256, 256>>>(z, emb);

    // numpy-exact Phi tick selection (float64 linspace semantics, first-wins argmin)
    double start = 1.0/12.0;
    double stop  = 1.0 - 1.0/12.0;
    double step  = (stop - start) / 3.0;
    double ticks[4];
    for (int i = 0; i < 4; i++) ticks[i] = (double)i * step + start;
    ticks[3] = stop;
    int pis[5];
    for (int si = 0; si < 5; si++){
        double target = (double)si / 4.0;
        int bestp = 0; double bestd = fabs(ticks[0] - target);
        for (int p = 1; p < 4; p++){
            double d = fabs(ticks[p] - target);
            if (d < bestd){ bestd = d; bestp = p; }
        }
        pis[si] = bestp;
    }

    const int scales[5] = {1, 2, 4, 8, 16};
    const int iofs[5]   = {0, 64, 320, 1344, 5440};
    // per-scale: splits + fmode (+TROWS: si>=3 uses 2 rows/thread)
    const int splits[5] = {32, 32, 16, 16, 8};
    const int fmodes[5] = {0, 0, 3, 2, 1};

    for (int si = 0; si < 5; si++){
        int ph = scales[si];
        int N  = B*ph*ph;
        if (si < 2) pool_kernel<<<(N*C + 255)/256, 256>>>(ph);
        int chunk = NE/splits[si];
        if (si >= 3){
            dim3 g((N + 255)/256, splits[si]);
            argmin_kernel<2><<<g, 128>>>(emb, N, chunk, iofs[si], fmodes[si]);
        } else {
            dim3 g((N + 127)/128, splits[si]);
            argmin_kernel<1><<<g, 128>>>(emb, N, chunk, iofs[si], fmodes[si]);
        }
        gather_kernel<<<(TOT + 255)/256, 256>>>(emb, si, ph, iofs[si]);
        conv_update_kernel<<<dim3(B, 4), 512>>>(z, phi_w + pis[si]*C*C*9, phi_b + pis[si]*C,
                                                si, (si == 4) ? out : (float*)0);
    }
    pack_kernel<<<(NIDX + 255)/256, 256>>>(out);
}

// round 10
// speedup vs baseline: 1.7891x; 1.0712x over previous
#include <cuda_runtime.h>
#include <cmath>

#define B 64
#define C 32
#define HW 16
#define IMG (C*HW*HW)        // 8192
#define TOT (B*IMG)          // 524288
#define NE 4096
#define NIDX 21824
#define ROWLEN 341
#define TCODES 128

// ---------------- scratch (no allocations allowed) ----------------
__device__ float g_zres[TOT];
__device__ float g_r[TOT];            // only scales 0..1 use this
__device__ float g_qup[TOT];
__device__ float g_hesq[NE];          // 0.5*||e||^2
__device__ unsigned long long g_res64[NIDX];
__device__ float g_losspart[5*256];
__device__ int   g_itab[4][16][4];
__device__ float g_wtab[4][16][4];

// ---------------- helpers ----------------
__device__ __forceinline__ float cubicw(float x){
    const float A = -0.75f;
    x = fabsf(x);
    if (x <= 1.f) return ((A + 2.f)*x - (A + 3.f))*x*x + 1.f;
    if (x < 2.f)  return A*(((x - 5.f)*x + 8.f)*x - 4.f);
    return 0.f;
}
__device__ __forceinline__ void ffma2(unsigned long long &d, unsigned long long a, unsigned long long b){
    asm("fma.rn.f32x2 %0, %1, %2, %0;" : "+l"(d) : "l"(a), "l"(b));
}
__device__ __forceinline__ unsigned long long pk2(float a, float b){
    return ((unsigned long long)__float_as_uint(b) << 32) | (unsigned long long)__float_as_uint(a);
}
__device__ __forceinline__ float lo2(unsigned long long v){ return __uint_as_float((unsigned)v); }
__device__ __forceinline__ float hi2(unsigned long long v){ return __uint_as_float((unsigned)(v >> 32)); }
__device__ __forceinline__ unsigned ford(float f){
    unsigned u = __float_as_uint(f);
    return (u & 0x80000000u) ? ~u : (u | 0x80000000u);
}

// pooled residual row loader. fmode: 0 = g_r, 1 = f=1, 2 = f=2, 3 = f=4
__device__ __forceinline__ void load_r(int row, int fmode, float* r){
    if (fmode == 1){
        int bb = row >> 8, rem = row & 255;
        const float* p = g_zres + bb*IMG + rem;
        #pragma unroll
        for (int c = 0; c < C; c++) r[c] = p[c*256];
    } else if (fmode == 2){
        int bb = row >> 6, rem = row & 63;
        int y = rem >> 3, x = rem & 7;
        const float* p = g_zres + bb*IMG + (2*y)*16 + 2*x;
        #pragma unroll
        for (int c = 0; c < C; c++){
            const float* q = p + c*256;
            r[c] = (q[0] + q[1] + q[16] + q[17]) * 0.25f;
        }
    } else if (fmode == 3){
        int bb = row >> 4, rem = row & 15;
        int y = rem >> 2, x = rem & 3;
        const float* p = g_zres + bb*IMG + (4*y)*16 + 4*x;
        #pragma unroll
        for (int c = 0; c < C; c++){
            const float* q = p + c*256;
            float s = 0.f;
            #pragma unroll
            for (int dy = 0; dy < 4; dy++){
                s += q[dy*16 + 0]; s += q[dy*16 + 1]; s += q[dy*16 + 2]; s += q[dy*16 + 3];
            }
            r[c] = s * 0.0625f;
        }
    } else {
        const float4* rp = (const float4*)(g_r + row*C);
        #pragma unroll
        for (int k = 0; k < 8; k++){
            float4 v = rp[k];
            r[4*k+0] = v.x; r[4*k+1] = v.y; r[4*k+2] = v.z; r[4*k+3] = v.w;
        }
    }
}

// ---------------- setup ----------------
__global__ void setup_kernel(const float* __restrict__ z, const float* __restrict__ emb){
    int t = blockIdx.x*blockDim.x + threadIdx.x;
    if (t < TOT) g_zres[t] = z[t];
    if (t < NIDX) g_res64[t] = 0xFFFFFFFFFFFFFFFFull;
    if (t < NE){
        float s = 0.f;
        #pragma unroll
        for (int k = 0; k < C; k++){ float e = emb[t*C + k]; s += e*e; }
        g_hesq[t] = 0.5f*s;
    }
    if (t < 256){
        int s = t >> 6, rem = t & 63, Y = rem >> 2, a = rem & 3;
        int ph = 1 << s;
        float scale = (float)ph / 16.f;
        float src = ((float)Y + 0.5f)*scale - 0.5f;
        float i0 = floorf(src);
        float fr = src - i0;
        int off = a - 1;
        int idx = (int)i0 + off;
        idx = min(max(idx, 0), ph - 1);
        g_itab[s][Y][a] = idx;
        g_wtab[s][Y][a] = cubicw(fr - (float)off);
    }
}

// ---------------- area pool to [N][C] channel-last (scales 0..1 only) ----------------
__global__ void pool_kernel(int ph){
    int t = blockIdx.x*blockDim.x + threadIdx.x;
    int N = B*ph*ph;
    if (t >= N*C) return;
    int n = t >> 5, c = t & 31;
    int pp = ph*ph;
    int b = n / pp, rem = n % pp, y = rem / ph, x = rem % ph;
    int f = HW / ph;
    const float* base = g_zres + ((b*C + c)*HW + y*f)*HW + x*f;
    float s = 0.f;
    for (int dy = 0; dy < f; dy++)
        for (int dx = 0; dx < f; dx++)
            s += base[dy*HW + dx];
    g_r[n*C + c] = s * (1.f / (float)(f*f));
}

// ---------------- code search: score = 0.5||e||^2 - r.e, FFMA2, TROWS rows/thread ----------------
template<int TROWS>
__global__ __launch_bounds__(128) void argmin_kernel(const float* __restrict__ emb, int N, int chunk,
                                                     int base, int fmode){
    __shared__ __align__(16) float et[C*TCODES];   // transposed [dim][code]
    __shared__ __align__(16) float hs[TCODES];
    int tid = threadIdx.x;
    int row0 = blockIdx.x*(128*TROWS) + tid;
    int cbase = blockIdx.y * chunk;

    unsigned long long nrp[TROWS][C];    // packed {-r_d, -r_d}
    bool act[TROWS];
    #pragma unroll
    for (int tr = 0; tr < TROWS; tr++){
        int row = row0 + tr*128;
        act[tr] = row < N;
        if (act[tr]){
            float r[C];
            load_r(row, fmode, r);
            #pragma unroll
            for (int c = 0; c < C; c++) nrp[tr][c] = pk2(-r[c], -r[c]);
        }
    }
    float best[TROWS]; int bcode[TROWS];
    #pragma unroll
    for (int tr = 0; tr < TROWS; tr++){ best[tr] = 3.4e38f; bcode[tr] = 0; }

    for (int tb = 0; tb < chunk; tb += TCODES){
        int code = cbase + tb + tid;
        const float4* src = (const float4*)(emb + code*C);
        __syncthreads();   // prior tile fully consumed
        #pragma unroll
        for (int k = 0; k < 8; k++){
            float4 v = src[k];
            et[(4*k+0)*TCODES + tid] = v.x;
            et[(4*k+1)*TCODES + tid] = v.y;
            et[(4*k+2)*TCODES + tid] = v.z;
            et[(4*k+3)*TCODES + tid] = v.w;
        }
        hs[tid] = g_hesq[code];
        __syncthreads();

        for (int jj = 0; jj < TCODES; jj += 8){
            const ulonglong2* h2 = (const ulonglong2*)(hs + jj);
            ulonglong2 ha = h2[0], hb = h2[1];
            unsigned long long acc[TROWS][4];
            #pragma unroll
            for (int tr = 0; tr < TROWS; tr++){
                acc[tr][0] = ha.x; acc[tr][1] = ha.y; acc[tr][2] = hb.x; acc[tr][3] = hb.y;
            }
            #pragma unroll
            for (int d = 0; d < C; d++){
                const ulonglong2* e2 = (const ulonglong2*)(et + d*TCODES + jj);
                ulonglong2 ea = e2[0], eb = e2[1];
                #pragma unroll
                for (int tr = 0; tr < TROWS; tr++){
                    ffma2(acc[tr][0], nrp[tr][d], ea.x);
                    ffma2(acc[tr][1], nrp[tr][d], ea.y);
                    ffma2(acc[tr][2], nrp[tr][d], eb.x);
                    ffma2(acc[tr][3], nrp[tr][d], eb.y);
                }
            }
            #pragma unroll
            for (int tr = 0; tr < TROWS; tr++){
                float s[8] = {lo2(acc[tr][0]),hi2(acc[tr][0]),lo2(acc[tr][1]),hi2(acc[tr][1]),
                              lo2(acc[tr][2]),hi2(acc[tr][2]),lo2(acc[tr][3]),hi2(acc[tr][3])};
                #pragma unroll
                for (int k = 0; k < 8; k++){
                    int cc = cbase + tb + jj + k;
                    if (s[k] < best[tr]){ best[tr] = s[k]; bcode[tr] = cc; }
                }
            }
        }
    }
    #pragma unroll
    for (int tr = 0; tr < TROWS; tr++){
        if (act[tr]){
            unsigned long long key = ((unsigned long long)ford(best[tr]) << 32) | (unsigned)bcode[tr];
            atomicMin(&g_res64[base + row0 + tr*128], key);
        }
    }
}

// ---------------- separable staged gather (si<4): block = (batch, 16-ch group) ----------------
__global__ __launch_bounds__(256) void gather_sep_kernel(const float* __restrict__ emb,
        int si, int ph, int lph, int base){
    __shared__ int   s_code[64];
    __shared__ float s_q[64*17];        // [code][17] padded
    __shared__ float s_tmp[16*8*16];    // [cl][py][x]
    int b = blockIdx.x, cg = blockIdx.y, t = threadIdx.x;
    int pp = ph*ph;

    if (t < pp) s_code[t] = (int)(g_res64[base + b*pp + t] & 0xFFFFFFFFull);
    __syncthreads();

    // stage q vectors: 16 channels per code
    for (int i = t; i < pp*16; i += 256){
        int code = s_code[i >> 4], cl = i & 15;
        s_q[(i >> 4)*17 + cl] = emb[code*C + cg*16 + cl];
    }
    __syncthreads();

    // pass1: x-interp -> s_tmp[cl][py][x]
    int n1 = 16*ph*16;
    for (int i = t; i < n1; i += 256){
        int x = i & 15;
        int py = (i >> 4) & (ph - 1);
        int cl = i >> (4 + lph);
        float acc = 0.f;
        #pragma unroll
        for (int ax = 0; ax < 4; ax++){
            int ix = g_itab[si][x][ax];
            acc += g_wtab[si][x][ax] * s_q[(py*ph + ix)*17 + cl];
        }
        s_tmp[(cl*8 + py)*16 + x] = acc;
    }
    __syncthreads();

    // pass2: y-interp -> g_qup
    for (int i = t; i < 4096; i += 256){
        int x = i & 15, y = (i >> 4) & 15, cl = i >> 8;
        float acc = 0.f;
        #pragma unroll
        for (int ay = 0; ay < 4; ay++){
            int iy = g_itab[si][y][ay];
            acc += g_wtab[si][y][ay] * s_tmp[(cl*8 + iy)*16 + x];
        }
        g_qup[((b*C + cg*16 + cl)*16 + y)*16 + x] = acc;
    }
}

// ---------------- direct gather (si=4 only) ----------------
__global__ void gather_direct_kernel(const float* __restrict__ emb, int base){
    int t = blockIdx.x*blockDim.x + threadIdx.x;
    if (t >= TOT) return;
    int x = t & 15, y = (t >> 4) & 15, c = (t >> 8) & 31, b = t >> 13;
    int n = (b*16 + y)*16 + x;
    int code = (int)(g_res64[base + n] & 0xFFFFFFFFull);
    g_qup[t] = emb[code*C + c];
}

// ---------------- Phi conv3x3 + residual update + loss (512 thr: oc8 x x16 x yq4) ----------------
// z_hat eliminated: z_hat == z - z_res, so loss d = -zres_new; out = z - zres_new.
__global__ __launch_bounds__(512) void conv_update_kernel(const float* __restrict__ z,
        const float* __restrict__ w, const float* __restrict__ bias, int si, float* __restrict__ out){
    __shared__ float s_in[C][HW][HW];   // 32 KB
    __shared__ float s_w[8*C*9];        // 9 KB
    __shared__ float red[512];          // 2 KB
    int b = blockIdx.x, og = blockIdx.y, t = threadIdx.x;

    const float4* gsrc = (const float4*)(g_qup + b*IMG);
    float4* sdst = (float4*)&s_in[0][0][0];
    for (int i = t; i < IMG/4; i += 512) sdst[i] = gsrc[i];
    for (int i = t; i < 8*C*9; i += 512) s_w[i] = w[og*8*C*9 + i];
    __syncthreads();

    int x    = t & 15;        // lane dimension -> conflict-free SMEM
    int yq   = (t >> 4) & 3;  // y-quarter: rows 4yq..4yq+3
    int oc_l = t >> 6;        // 0..7
    int y0 = 4*yq;

    float acc0 = 0.f, acc1 = 0.f, acc2 = 0.f, acc3 = 0.f;

    for (int ci = 0; ci < C; ci++){
        #pragma unroll
        for (int kx = 0; kx < 3; kx++){
            int xx = x + kx - 1;
            if (xx < 0 || xx >= HW) continue;   // zero pad
            const float* wp = s_w + (oc_l*C + ci)*9 + kx;
            float w0 = wp[0], w1 = wp[3], w2 = wp[6];
            float v0 = (y0 >= 1)      ? s_in[ci][y0-1][xx] : 0.f;
            float v1 = s_in[ci][y0+0][xx];
            float v2 = s_in[ci][y0+1][xx];
            float v3 = s_in[ci][y0+2][xx];
            float v4 = s_in[ci][y0+3][xx];
            float v5 = (y0 + 4 < HW)  ? s_in[ci][y0+4][xx] : 0.f;
            acc0 += w0*v0 + w1*v1 + w2*v2;
            acc1 += w0*v1 + w1*v2 + w2*v3;
            acc2 += w0*v2 + w1*v3 + w2*v4;
            acc3 += w0*v3 + w1*v4 + w2*v5;
        }
    }

    int oc = og*8 + oc_l;
    float bval = bias[oc];
    float ls = 0.f;
    int gbase = ((b*C + oc)*HW)*HW + x;
    float accs[4] = {acc0, acc1, acc2, acc3};
    #pragma unroll
    for (int i = 0; i < 4; i++){
        int y = y0 + i;
        float qv = 0.5f*s_in[oc][y][x] + 0.5f*(accs[i] + bval);
        int g = gbase + y*HW;
        float zr = g_zres[g] - qv;
        if (si < 4){
            g_zres[g] = zr;
        } else {
            out[g] = z[g] - zr;   // z_hat (straight-through value)
        }
        ls += zr*zr;              // (z_hat - z)^2 == zres_new^2
    }
    red[t] = ls;
    __syncthreads();
    for (int s = 256; s > 0; s >>= 1){
        if (t < s) red[t] += red[t+s];
        __syncthreads();
    }
    if (t == 0) g_losspart[si*256 + b*4 + og] = red[0];
}

// ---------------- final pack: loss (parallel reduce) + idx floats ----------------
__global__ void pack_kernel(float* __restrict__ out){
    int t = blockIdx.x*blockDim.x + threadIdx.x;
    if (blockIdx.x == 0){
        __shared__ float red[256];
        float s = 0.f;
        for (int i = threadIdx.x; i < 5*256; i += 256) s += g_losspart[i];
        red[threadIdx.x] = s;
        __syncthreads();
        for (int k = 128; k > 0; k >>= 1){
            if (threadIdx.x < k) red[threadIdx.x] += red[threadIdx.x + k];
            __syncthreads();
        }
        if (threadIdx.x == 0) out[TOT] = red[0] * (1.25f / ((float)TOT * 5.f));
    }
    if (t < NIDX){
        int base, pp, ofs_row;
        if      (t <   64){ base=0;    pp=1;   ofs_row=0;  }
        else if (t <  320){ base=64;   pp=4;   ofs_row=1;  }
        else if (t < 1344){ base=320;  pp=16;  ofs_row=5;  }
        else if (t < 5440){ base=1344; pp=64;  ofs_row=21; }
        else              { base=5440; pp=256; ofs_row=85; }
        int r = t - base;
        int bb = r / pp, p = r % pp;
        int code = (int)(g_res64[t] & 0xFFFFFFFFull);
        out[TOT + 1 + bb*ROWLEN + ofs_row + p] = (float)code;
    }
}

extern "C" void kernel_launch(void* const* d_in, const int* in_sizes, int n_in,
                              void* d_out, int out_size){
    // Bind inputs by element count: z=524288, emb=131072, phi_w=36864, phi_b=128 (all distinct).
    const float* z = 0; const float* emb = 0; const float* phi_w = 0; const float* phi_b = 0;
    for (int i = 0; i < n_in; i++){
        switch (in_sizes[i]){
            case 524288: z     = (const float*)d_in[i]; break;
            case 131072: emb   = (const float*)d_in[i]; break;
            case 36864:  phi_w = (const float*)d_in[i]; break;
            case 128:    phi_b = (const float*)d_in[i]; break;
            default: break;
        }
    }
    float* out = (float*)d_out;
    (void)out_size;

    setup_kernel<<<(TOT + 255)/256, 256>>>(z, emb);

    // numpy-exact Phi tick selection (float64 linspace semantics, first-wins argmin)
    double start = 1.0/12.0;
    double stop  = 1.0 - 1.0/12.0;
    double step  = (stop - start) / 3.0;
    double ticks[4];
    for (int i = 0; i < 4; i++) ticks[i] = (double)i * step + start;
    ticks[3] = stop;
    int pis[5];
    for (int si = 0; si < 5; si++){
        double target = (double)si / 4.0;
        int bestp = 0; double bestd = fabs(ticks[0] - target);
        for (int p = 1; p < 4; p++){
            double d = fabs(ticks[p] - target);
            if (d < bestd){ bestd = d; bestp = p; }
        }
        pis[si] = bestp;
    }

    const int scales[5] = {1, 2, 4, 8, 16};
    const int iofs[5]   = {0, 64, 320, 1344, 5440};
    const int splits[5] = {32, 32, 16, 16, 8};
    const int fmodes[5] = {0, 0, 3, 2, 1};

    for (int si = 0; si < 5; si++){
        int ph = scales[si];
        int N  = B*ph*ph;
        if (si < 2) pool_kernel<<<(N*C + 255)/256, 256>>>(ph);
        int chunk = NE/splits[si];
        if (si >= 3){
            dim3 g((N + 255)/256, splits[si]);
            argmin_kernel<2><<<g, 128>>>(emb, N, chunk, iofs[si], fmodes[si]);
        } else {
            dim3 g((N + 127)/128, splits[si]);
            argmin_kernel<1><<<g, 128>>>(emb, N, chunk, iofs[si], fmodes[si]);
        }
        if (si < 4)
            gather_sep_kernel<<<dim3(B, 2), 256>>>(emb, si, ph, si, iofs[si]);
        else
            gather_direct_kernel<<<(TOT + 255)/256, 256>>>(emb, iofs[si]);
        conv_update_kernel<<<dim3(B, 4), 512>>>(z, phi_w + pis[si]*C*C*9, phi_b + pis[si]*C,
                                                si, (si == 4) ? out : (float*)0);
    }
    pack_kernel<<<(NIDX + 255)/256, 256>>>(out);
}

// round 11
// speedup vs baseline: 1.9489x; 1.0893x over previous
#include <cuda_runtime.h>
#include <cmath>

#define B 64
#define C 32
#define HW 16
#define IMG (C*HW*HW)        // 8192
#define TOT (B*IMG)          // 524288
#define NE 4096
#define NIDX 21824
#define ROWLEN 341
#define TCODES 128

// ---------------- scratch (no allocations allowed) ----------------
__device__ float g_zres[TOT];
__device__ float g_r[TOT];            // only scales 0..1 use this
__device__ float g_qup[TOT];          // layout [b][y][x][c] (channel-last)
__device__ float g_hesq[NE];          // 0.5*||e||^2
__device__ unsigned long long g_res64[NIDX];
__device__ float g_losspart[5*256];
__device__ int   g_itab[4][16][4];
__device__ float g_wtab[4][16][4];

// ---------------- helpers ----------------
__device__ __forceinline__ float cubicw(float x){
    const float A = -0.75f;
    x = fabsf(x);
    if (x <= 1.f) return ((A + 2.f)*x - (A + 3.f))*x*x + 1.f;
    if (x < 2.f)  return A*(((x - 5.f)*x + 8.f)*x - 4.f);
    return 0.f;
}
__device__ __forceinline__ void ffma2(unsigned long long &d, unsigned long long a, unsigned long long b){
    asm("fma.rn.f32x2 %0, %1, %2, %0;" : "+l"(d) : "l"(a), "l"(b));
}
__device__ __forceinline__ unsigned long long pk2(float a, float b){
    return ((unsigned long long)__float_as_uint(b) << 32) | (unsigned long long)__float_as_uint(a);
}
__device__ __forceinline__ float lo2(unsigned long long v){ return __uint_as_float((unsigned)v); }
__device__ __forceinline__ float hi2(unsigned long long v){ return __uint_as_float((unsigned)(v >> 32)); }
__device__ __forceinline__ unsigned ford(float f){
    unsigned u = __float_as_uint(f);
    return (u & 0x80000000u) ? ~u : (u | 0x80000000u);
}

// pooled residual row loader. fmode: 0 = g_r, 1 = f=1, 2 = f=2, 3 = f=4
__device__ __forceinline__ void load_r(int row, int fmode, float* r){
    if (fmode == 1){
        int bb = row >> 8, rem = row & 255;
        const float* p = g_zres + bb*IMG + rem;
        #pragma unroll
        for (int c = 0; c < C; c++) r[c] = p[c*256];
    } else if (fmode == 2){
        int bb = row >> 6, rem = row & 63;
        int y = rem >> 3, x = rem & 7;
        const float* p = g_zres + bb*IMG + (2*y)*16 + 2*x;
        #pragma unroll
        for (int c = 0; c < C; c++){
            const float* q = p + c*256;
            r[c] = (q[0] + q[1] + q[16] + q[17]) * 0.25f;
        }
    } else if (fmode == 3){
        int bb = row >> 4, rem = row & 15;
        int y = rem >> 2, x = rem & 3;
        const float* p = g_zres + bb*IMG + (4*y)*16 + 4*x;
        #pragma unroll
        for (int c = 0; c < C; c++){
            const float* q = p + c*256;
            float s = 0.f;
            #pragma unroll
            for (int dy = 0; dy < 4; dy++){
                s += q[dy*16 + 0]; s += q[dy*16 + 1]; s += q[dy*16 + 2]; s += q[dy*16 + 3];
            }
            r[c] = s * 0.0625f;
        }
    } else {
        const float4* rp = (const float4*)(g_r + row*C);
        #pragma unroll
        for (int k = 0; k < 8; k++){
            float4 v = rp[k];
            r[4*k+0] = v.x; r[4*k+1] = v.y; r[4*k+2] = v.z; r[4*k+3] = v.w;
        }
    }
}

// ---------------- setup (also pools scale 0, whose input is raw z) ----------------
__global__ void setup_kernel(const float* __restrict__ z, const float* __restrict__ emb){
    int t = blockIdx.x*blockDim.x + threadIdx.x;
    if (t < TOT) g_zres[t] = z[t];
    if (t < NIDX) g_res64[t] = 0xFFFFFFFFFFFFFFFFull;
    if (t < NE){
        float s = 0.f;
        #pragma unroll
        for (int k = 0; k < C; k++){ float e = emb[t*C + k]; s += e*e; }
        g_hesq[t] = 0.5f*s;
    }
    if (t < 2048){   // pool scale 0 (f=16): r[b][c] = mean z[b][c][:][:]
        int b = t >> 5, c = t & 31;
        const float4* p = (const float4*)(z + (b*C + c)*256);
        float s = 0.f;
        for (int k = 0; k < 64; k++){
            float4 v = p[k];
            s += v.x + v.y + v.z + v.w;
        }
        g_r[(b)*C + c] = s * (1.f/256.f);
    }
    if (t < 256){
        int s = t >> 6, rem = t & 63, Y = rem >> 2, a = rem & 3;
        int ph = 1 << s;
        float scale = (float)ph / 16.f;
        float src = ((float)Y + 0.5f)*scale - 0.5f;
        float i0 = floorf(src);
        float fr = src - i0;
        int off = a - 1;
        int idx = (int)i0 + off;
        idx = min(max(idx, 0), ph - 1);
        g_itab[s][Y][a] = idx;
        g_wtab[s][Y][a] = cubicw(fr - (float)off);
    }
}

// ---------------- area pool to [N][C] channel-last (scale 1 only) ----------------
__global__ void pool_kernel(int ph){
    int t = blockIdx.x*blockDim.x + threadIdx.x;
    int N = B*ph*ph;
    if (t >= N*C) return;
    int n = t >> 5, c = t & 31;
    int pp = ph*ph;
    int b = n / pp, rem = n % pp, y = rem / ph, x = rem % ph;
    int f = HW / ph;
    const float* base = g_zres + ((b*C + c)*HW + y*f)*HW + x*f;
    float s = 0.f;
    for (int dy = 0; dy < f; dy++)
        for (int dx = 0; dx < f; dx++)
            s += base[dy*HW + dx];
    g_r[n*C + c] = s * (1.f / (float)(f*f));
}

// ---------------- code search: score = 0.5||e||^2 - r.e, FFMA2, TROWS rows/thread ----------------
template<int TROWS>
__global__ __launch_bounds__(128) void argmin_kernel(const float* __restrict__ emb, int N, int chunk,
                                                     int base, int fmode){
    __shared__ __align__(16) float et[C*TCODES];   // transposed [dim][code]
    __shared__ __align__(16) float hs[TCODES];
    int tid = threadIdx.x;
    int row0 = blockIdx.x*(128*TROWS) + tid;
    int cbase = blockIdx.y * chunk;

    unsigned long long nrp[TROWS][C];    // packed {-r_d, -r_d}
    bool act[TROWS];
    #pragma unroll
    for (int tr = 0; tr < TROWS; tr++){
        int row = row0 + tr*128;
        act[tr] = row < N;
        if (act[tr]){
            float r[C];
            load_r(row, fmode, r);
            #pragma unroll
            for (int c = 0; c < C; c++) nrp[tr][c] = pk2(-r[c], -r[c]);
        }
    }
    float best[TROWS]; int bcode[TROWS];
    #pragma unroll
    for (int tr = 0; tr < TROWS; tr++){ best[tr] = 3.4e38f; bcode[tr] = 0; }

    for (int tb = 0; tb < chunk; tb += TCODES){
        int code = cbase + tb + tid;
        const float4* src = (const float4*)(emb + code*C);
        __syncthreads();   // prior tile fully consumed
        #pragma unroll
        for (int k = 0; k < 8; k++){
            float4 v = src[k];
            et[(4*k+0)*TCODES + tid] = v.x;
            et[(4*k+1)*TCODES + tid] = v.y;
            et[(4*k+2)*TCODES + tid] = v.z;
            et[(4*k+3)*TCODES + tid] = v.w;
        }
        hs[tid] = g_hesq[code];
        __syncthreads();

        for (int jj = 0; jj < TCODES; jj += 8){
            const ulonglong2* h2 = (const ulonglong2*)(hs + jj);
            ulonglong2 ha = h2[0], hb = h2[1];
            unsigned long long acc[TROWS][4];
            #pragma unroll
            for (int tr = 0; tr < TROWS; tr++){
                acc[tr][0] = ha.x; acc[tr][1] = ha.y; acc[tr][2] = hb.x; acc[tr][3] = hb.y;
            }
            #pragma unroll
            for (int d = 0; d < C; d++){
                const ulonglong2* e2 = (const ulonglong2*)(et + d*TCODES + jj);
                ulonglong2 ea = e2[0], eb = e2[1];
                #pragma unroll
                for (int tr = 0; tr < TROWS; tr++){
                    ffma2(acc[tr][0], nrp[tr][d], ea.x);
                    ffma2(acc[tr][1], nrp[tr][d], ea.y);
                    ffma2(acc[tr][2], nrp[tr][d], eb.x);
                    ffma2(acc[tr][3], nrp[tr][d], eb.y);
                }
            }
            #pragma unroll
            for (int tr = 0; tr < TROWS; tr++){
                float s[8] = {lo2(acc[tr][0]),hi2(acc[tr][0]),lo2(acc[tr][1]),hi2(acc[tr][1]),
                              lo2(acc[tr][2]),hi2(acc[tr][2]),lo2(acc[tr][3]),hi2(acc[tr][3])};
                #pragma unroll
                for (int k = 0; k < 8; k++){
                    int cc = cbase + tb + jj + k;
                    if (s[k] < best[tr]){ best[tr] = s[k]; bcode[tr] = cc; }
                }
            }
        }
    }
    #pragma unroll
    for (int tr = 0; tr < TROWS; tr++){
        if (act[tr]){
            unsigned long long key = ((unsigned long long)ford(best[tr]) << 32) | (unsigned)bcode[tr];
            atomicMin(&g_res64[base + row0 + tr*128], key);
        }
    }
}

// ---------------- separable staged gather (si<4) -> g_qup [b][y][x][c] ----------------
__global__ __launch_bounds__(256) void gather_sep_kernel(const float* __restrict__ emb,
        int si, int ph, int lph, int base){
    __shared__ int   s_code[64];
    __shared__ float s_q[64*17];          // [code][cl + pad]
    __shared__ float s_tmp[8*16*17];      // [py][x][cl + pad]
    int b = blockIdx.x, cg = blockIdx.y, t = threadIdx.x;
    int pp = ph*ph;

    if (t < pp) s_code[t] = (int)(g_res64[base + b*pp + t] & 0xFFFFFFFFull);
    __syncthreads();

    // stage q vectors: lanes vary cl -> coalesced emb reads
    for (int i = t; i < pp*16; i += 256){
        int cl = i & 15, code = i >> 4;
        s_q[code*17 + cl] = emb[s_code[code]*C + cg*16 + cl];
    }
    __syncthreads();

    // pass1: x-interp -> s_tmp[py][x][cl]
    int n1 = ph*256;
    for (int i = t; i < n1; i += 256){
        int cl = i & 15, x = (i >> 4) & 15, py = i >> 8;
        float acc = 0.f;
        #pragma unroll
        for (int ax = 0; ax < 4; ax++){
            int ix = g_itab[si][x][ax];
            acc += g_wtab[si][x][ax] * s_q[(py*ph + ix)*17 + cl];
        }
        s_tmp[(py*16 + x)*17 + cl] = acc;
    }
    __syncthreads();

    // pass2: y-interp -> g_qup[b][y][x][cg*16+cl] (coalesced)
    for (int i = t; i < 4096; i += 256){
        int cl = i & 15, x = (i >> 4) & 15, y = i >> 8;
        float acc = 0.f;
        #pragma unroll
        for (int ay = 0; ay < 4; ay++){
            int iy = g_itab[si][y][ay];
            acc += g_wtab[si][y][ay] * s_tmp[(iy*16 + x)*17 + cl];
        }
        g_qup[b*IMG + (y*16 + x)*32 + cg*16 + cl] = acc;
    }
}

// ---------------- direct gather (si=4): lanes vary c -> fully coalesced ----------------
__global__ void gather_direct_kernel(const float* __restrict__ emb, int base){
    int t = blockIdx.x*blockDim.x + threadIdx.x;
    if (t >= TOT) return;
    int c = t & 31, pix = (t >> 5) & 255, b = t >> 13;
    int code = (int)(g_res64[base + b*256 + pix] & 0xFFFFFFFFull);
    g_qup[t] = emb[code*C + c];   // g_qup [b][y][x][c]
}

// ---------------- Phi conv3x3 + residual update + loss (512 thr: oc8 x x16 x yq4) ----------------
// z_hat eliminated: z_hat == z - z_res; q_up arrives channel-last, transposed into padded SMEM.
__global__ __launch_bounds__(512) void conv_update_kernel(const float* __restrict__ z,
        const float* __restrict__ w, const float* __restrict__ bias, int si, float* __restrict__ out){
    __shared__ float s_in[C*257];       // [ci][y*16+x], pad 1 per ci
    __shared__ float s_w[8*C*12];       // [oc_l*C+ci][12] padded for float4 loads
    __shared__ float red[512];
    int b = blockIdx.x, og = blockIdx.y, t = threadIdx.x;

    // load q_up [y][x][c] -> s_in[c][y*16+x]  (bank-conflict-free: banks = c0+k+pix mod 32)
    const float4* gsrc = (const float4*)(g_qup + b*IMG);
    for (int j = t; j < IMG/4; j += 512){
        float4 v = gsrc[j];
        int pix = j >> 3, c0 = (j & 7)*4;
        s_in[(c0+0)*257 + pix] = v.x;
        s_in[(c0+1)*257 + pix] = v.y;
        s_in[(c0+2)*257 + pix] = v.z;
        s_in[(c0+3)*257 + pix] = v.w;
    }
    for (int i = t; i < 8*C*9; i += 512){
        s_w[(i/9)*12 + (i%9)] = w[og*8*C*9 + i];
    }
    __syncthreads();

    int x    = t & 15;        // lane dimension -> conflict-free SMEM
    int yq   = (t >> 4) & 3;  // y-quarter: rows 4yq..4yq+3
    int oc_l = t >> 6;        // 0..7
    int y0 = 4*yq;

    float acc0 = 0.f, acc1 = 0.f, acc2 = 0.f, acc3 = 0.f;

    for (int ci = 0; ci < C; ci++){
        const float* base_ci = s_in + ci*257;
        const float* wq = s_w + (oc_l*C + ci)*12;
        float4 wa = *(const float4*)(wq);       // w[0..3]
        float4 wb = *(const float4*)(wq + 4);   // w[4..7]
        float w8  = wq[8];
        float wreg[9] = {wa.x, wa.y, wa.z, wa.w, wb.x, wb.y, wb.z, wb.w, w8};
        #pragma unroll
        for (int kx = 0; kx < 3; kx++){
            int xx = x + kx - 1;
            if (xx < 0 || xx >= HW) continue;   // zero pad
            float w0 = wreg[kx], w1 = wreg[kx+3], w2 = wreg[kx+6];
            float v0 = (y0 >= 1)      ? base_ci[(y0-1)*16 + xx] : 0.f;
            float v1 = base_ci[(y0+0)*16 + xx];
            float v2 = base_ci[(y0+1)*16 + xx];
            float v3 = base_ci[(y0+2)*16 + xx];
            float v4 = base_ci[(y0+3)*16 + xx];
            float v5 = (y0 + 4 < HW)  ? base_ci[(y0+4)*16 + xx] : 0.f;
            acc0 += w0*v0 + w1*v1 + w2*v2;
            acc1 += w0*v1 + w1*v2 + w2*v3;
            acc2 += w0*v2 + w1*v3 + w2*v4;
            acc3 += w0*v3 + w1*v4 + w2*v5;
        }
    }

    int oc = og*8 + oc_l;
    float bval = bias[oc];
    float ls = 0.f;
    int gbase = ((b*C + oc)*HW)*HW + x;
    float accs[4] = {acc0, acc1, acc2, acc3};
    #pragma unroll
    for (int i = 0; i < 4; i++){
        int y = y0 + i;
        float qv = 0.5f*s_in[oc*257 + y*16 + x] + 0.5f*(accs[i] + bval);
        int g = gbase + y*HW;
        float zr = g_zres[g] - qv;
        if (si < 4){
            g_zres[g] = zr;
        } else {
            out[g] = z[g] - zr;   // z_hat (straight-through value)
        }
        ls += zr*zr;              // (z_hat - z)^2 == zres_new^2
    }
    red[t] = ls;
    __syncthreads();
    for (int s = 256; s > 0; s >>= 1){
        if (t < s) red[t] += red[t+s];
        __syncthreads();
    }
    if (t == 0) g_losspart[si*256 + b*4 + og] = red[0];
}

// ---------------- final pack: loss (parallel reduce) + idx floats ----------------
__global__ void pack_kernel(float* __restrict__ out){
    int t = blockIdx.x*blockDim.x + threadIdx.x;
    if (blockIdx.x == 0){
        __shared__ float red[256];
        float s = 0.f;
        for (int i = threadIdx.x; i < 5*256; i += 256) s += g_losspart[i];
        red[threadIdx.x] = s;
        __syncthreads();
        for (int k = 128; k > 0; k >>= 1){
            if (threadIdx.x < k) red[threadIdx.x] += red[threadIdx.x + k];
            __syncthreads();
        }
        if (threadIdx.x == 0) out[TOT] = red[0] * (1.25f / ((float)TOT * 5.f));
    }
    if (t < NIDX){
        int base, pp, ofs_row;
        if      (t <   64){ base=0;    pp=1;   ofs_row=0;  }
        else if (t <  320){ base=64;   pp=4;   ofs_row=1;  }
        else if (t < 1344){ base=320;  pp=16;  ofs_row=5;  }
        else if (t < 5440){ base=1344; pp=64;  ofs_row=21; }
        else              { base=5440; pp=256; ofs_row=85; }
        int r = t - base;
        int bb = r / pp, p = r % pp;
        int code = (int)(g_res64[t] & 0xFFFFFFFFull);
        out[TOT + 1 + bb*ROWLEN + ofs_row + p] = (float)code;
    }
}

extern "C" void kernel_launch(void* const* d_in, const int* in_sizes, int n_in,
                              void* d_out, int out_size){
    // Bind inputs by element count: z=524288, emb=131072, phi_w=36864, phi_b=128 (all distinct).
    const float* z = 0; const float* emb = 0; const float* phi_w = 0; const float* phi_b = 0;
    for (int i = 0; i < n_in; i++){
        switch (in_sizes[i]){
            case 524288: z     = (const float*)d_in[i]; break;
            case 131072: emb   = (const float*)d_in[i]; break;
            case 36864:  phi_w = (const float*)d_in[i]; break;
            case 128:    phi_b = (const float*)d_in[i]; break;
            default: break;
        }
    }
    float* out = (float*)d_out;
    (void)out_size;

    setup_kernel<<<(TOT + 255)/256, 256>>>(z, emb);

    // numpy-exact Phi tick selection (float64 linspace semantics, first-wins argmin)
    double start = 1.0/12.0;
    double stop  = 1.0 - 1.0/12.0;
    double step  = (stop - start) / 3.0;
    double ticks[4];
    for (int i = 0; i < 4; i++) ticks[i] = (double)i * step + start;
    ticks[3] = stop;
    int pis[5];
    for (int si = 0; si < 5; si++){
        double target = (double)si / 4.0;
        int bestp = 0; double bestd = fabs(ticks[0] - target);
        for (int p = 1; p < 4; p++){
            double d = fabs(ticks[p] - target);
            if (d < bestd){ bestd = d; bestp = p; }
        }
        pis[si] = bestp;
    }

    const int scales[5] = {1, 2, 4, 8, 16};
    const int iofs[5]   = {0, 64, 320, 1344, 5440};
    const int splits[5] = {32, 32, 16, 16, 8};
    const int fmodes[5] = {0, 0, 3, 2, 1};

    for (int si = 0; si < 5; si++){
        int ph = scales[si];
        int N  = B*ph*ph;
        if (si == 1) pool_kernel<<<(N*C + 255)/256, 256>>>(ph);
        int chunk = NE/splits[si];
        if (si >= 3){
            dim3 g((N + 255)/256, splits[si]);
            argmin_kernel<2><<<g, 128>>>(emb, N, chunk, iofs[si], fmodes[si]);
        } else {
            dim3 g((N + 127)/128, splits[si]);
            argmin_kernel<1><<<g, 128>>>(emb, N, chunk, iofs[si], fmodes[si]);
        }
        if (si < 4)
            gather_sep_kernel<<<dim3(B, 2), 256>>>(emb, si, ph, si, iofs[si]);
        else
            gather_direct_kernel<<<(TOT + 255)/256, 256>>>(emb, iofs[si]);
        conv_update_kernel<<<dim3(B, 4), 512>>>(z, phi_w + pis[si]*C*C*9, phi_b + pis[si]*C,
                                                si, (si == 4) ? out : (float*)0);
    }
    pack_kernel<<<(NIDX + 255)/256, 256>>>(out);
}

// round 12
// speedup vs baseline: 2.0774x; 1.0659x over previous
#include <cuda_runtime.h>
#include <cmath>

#define B 64
#define C 32
#define HW 16
#define IMG (C*HW*HW)        // 8192
#define TOT (B*IMG)          // 524288
#define NE 4096
#define NIDX 21824
#define ROWLEN 341
#define TCODES 128

// ---------------- scratch (no allocations allowed) ----------------
__device__ float g_zres[TOT];
__device__ float g_r[TOT];            // only scales 0..1 use this
__device__ float g_qup[TOT];          // layout [b][y][x][c] (channel-last)
__device__ float g_hesq[NE];          // 0.5*||e||^2
__device__ unsigned long long g_res64[NIDX];
__device__ float g_losspart[5*256];
__device__ int   g_itab[4][16][4];
__device__ float g_wtab[4][16][4];

// ---------------- helpers ----------------
__device__ __forceinline__ float cubicw(float x){
    const float A = -0.75f;
    x = fabsf(x);
    if (x <= 1.f) return ((A + 2.f)*x - (A + 3.f))*x*x + 1.f;
    if (x < 2.f)  return A*(((x - 5.f)*x + 8.f)*x - 4.f);
    return 0.f;
}
__device__ __forceinline__ void ffma2(unsigned long long &d, unsigned long long a, unsigned long long b){
    asm("fma.rn.f32x2 %0, %1, %2, %0;" : "+l"(d) : "l"(a), "l"(b));
}
__device__ __forceinline__ unsigned long long pk2(float a, float b){
    return ((unsigned long long)__float_as_uint(b) << 32) | (unsigned long long)__float_as_uint(a);
}
__device__ __forceinline__ float lo2(unsigned long long v){ return __uint_as_float((unsigned)v); }
__device__ __forceinline__ float hi2(unsigned long long v){ return __uint_as_float((unsigned)(v >> 32)); }
__device__ __forceinline__ unsigned ford(float f){
    unsigned u = __float_as_uint(f);
    return (u & 0x80000000u) ? ~u : (u | 0x80000000u);
}

// pooled residual row loader. fmode: 0 = g_r, 1 = f=1, 2 = f=2, 3 = f=4
__device__ __forceinline__ void load_r(int row, int fmode, float* r){
    if (fmode == 1){
        int bb = row >> 8, rem = row & 255;
        const float* p = g_zres + bb*IMG + rem;
        #pragma unroll
        for (int c = 0; c < C; c++) r[c] = p[c*256];
    } else if (fmode == 2){
        int bb = row >> 6, rem = row & 63;
        int y = rem >> 3, x = rem & 7;
        const float* p = g_zres + bb*IMG + (2*y)*16 + 2*x;
        #pragma unroll
        for (int c = 0; c < C; c++){
            const float* q = p + c*256;
            r[c] = (q[0] + q[1] + q[16] + q[17]) * 0.25f;
        }
    } else if (fmode == 3){
        int bb = row >> 4, rem = row & 15;
        int y = rem >> 2, x = rem & 3;
        const float* p = g_zres + bb*IMG + (4*y)*16 + 4*x;
        #pragma unroll
        for (int c = 0; c < C; c++){
            const float* q = p + c*256;
            float s = 0.f;
            #pragma unroll
            for (int dy = 0; dy < 4; dy++){
                s += q[dy*16 + 0]; s += q[dy*16 + 1]; s += q[dy*16 + 2]; s += q[dy*16 + 3];
            }
            r[c] = s * 0.0625f;
        }
    } else {
        const float4* rp = (const float4*)(g_r + row*C);
        #pragma unroll
        for (int k = 0; k < 8; k++){
            float4 v = rp[k];
            r[4*k+0] = v.x; r[4*k+1] = v.y; r[4*k+2] = v.z; r[4*k+3] = v.w;
        }
    }
}

// ---------------- setup (also pools scale 0, whose input is raw z) ----------------
__global__ void setup_kernel(const float* __restrict__ z, const float* __restrict__ emb){
    int t = blockIdx.x*blockDim.x + threadIdx.x;
    if (t < TOT) g_zres[t] = z[t];
    if (t < NIDX) g_res64[t] = 0xFFFFFFFFFFFFFFFFull;
    if (t < NE){
        float s = 0.f;
        #pragma unroll
        for (int k = 0; k < C; k++){ float e = emb[t*C + k]; s += e*e; }
        g_hesq[t] = 0.5f*s;
    }
    if (t < 2048){   // pool scale 0 (f=16): r[b][c] = mean z[b][c][:][:]
        int b = t >> 5, c = t & 31;
        const float4* p = (const float4*)(z + (b*C + c)*256);
        float s = 0.f;
        for (int k = 0; k < 64; k++){
            float4 v = p[k];
            s += v.x + v.y + v.z + v.w;
        }
        g_r[(b)*C + c] = s * (1.f/256.f);
    }
    if (t < 256){
        int s = t >> 6, rem = t & 63, Y = rem >> 2, a = rem & 3;
        int ph = 1 << s;
        float scale = (float)ph / 16.f;
        float src = ((float)Y + 0.5f)*scale - 0.5f;
        float i0 = floorf(src);
        float fr = src - i0;
        int off = a - 1;
        int idx = (int)i0 + off;
        idx = min(max(idx, 0), ph - 1);
        g_itab[s][Y][a] = idx;
        g_wtab[s][Y][a] = cubicw(fr - (float)off);
    }
}

// ---------------- area pool to [N][C] channel-last (scale 1 only) ----------------
__global__ void pool_kernel(int ph){
    int t = blockIdx.x*blockDim.x + threadIdx.x;
    int N = B*ph*ph;
    if (t >= N*C) return;
    int n = t >> 5, c = t & 31;
    int pp = ph*ph;
    int b = n / pp, rem = n % pp, y = rem / ph, x = rem % ph;
    int f = HW / ph;
    const float* base = g_zres + ((b*C + c)*HW + y*f)*HW + x*f;
    float s = 0.f;
    for (int dy = 0; dy < f; dy++)
        for (int dx = 0; dx < f; dx++)
            s += base[dy*HW + dx];
    g_r[n*C + c] = s * (1.f / (float)(f*f));
}

// ---------------- code search: score = 0.5||e||^2 - r.e, FFMA2, TROWS rows/thread ----------------
template<int TROWS>
__global__ __launch_bounds__(128) void argmin_kernel(const float* __restrict__ emb, int N, int chunk,
                                                     int base, int fmode){
    __shared__ __align__(16) float et[C*TCODES];   // transposed [dim][code]
    __shared__ __align__(16) float hs[TCODES];
    int tid = threadIdx.x;
    int row0 = blockIdx.x*(128*TROWS) + tid;
    int cbase = blockIdx.y * chunk;

    unsigned long long nrp[TROWS][C];    // packed {-r_d, -r_d}
    bool act[TROWS];
    #pragma unroll
    for (int tr = 0; tr < TROWS; tr++){
        int row = row0 + tr*128;
        act[tr] = row < N;
        if (act[tr]){
            float r[C];
            load_r(row, fmode, r);
            #pragma unroll
            for (int c = 0; c < C; c++) nrp[tr][c] = pk2(-r[c], -r[c]);
        }
    }
    float best[TROWS]; int bcode[TROWS];
    #pragma unroll
    for (int tr = 0; tr < TROWS; tr++){ best[tr] = 3.4e38f; bcode[tr] = 0; }

    for (int tb = 0; tb < chunk; tb += TCODES){
        int code = cbase + tb + tid;
        const float4* src = (const float4*)(emb + code*C);
        __syncthreads();   // prior tile fully consumed
        #pragma unroll
        for (int k = 0; k < 8; k++){
            float4 v = src[k];
            et[(4*k+0)*TCODES + tid] = v.x;
            et[(4*k+1)*TCODES + tid] = v.y;
            et[(4*k+2)*TCODES + tid] = v.z;
            et[(4*k+3)*TCODES + tid] = v.w;
        }
        hs[tid] = g_hesq[code];
        __syncthreads();

        for (int jj = 0; jj < TCODES; jj += 8){
            const ulonglong2* h2 = (const ulonglong2*)(hs + jj);
            ulonglong2 ha = h2[0], hb = h2[1];
            unsigned long long acc[TROWS][4];
            #pragma unroll
            for (int tr = 0; tr < TROWS; tr++){
                acc[tr][0] = ha.x; acc[tr][1] = ha.y; acc[tr][2] = hb.x; acc[tr][3] = hb.y;
            }
            #pragma unroll
            for (int d = 0; d < C; d++){
                const ulonglong2* e2 = (const ulonglong2*)(et + d*TCODES + jj);
                ulonglong2 ea = e2[0], eb = e2[1];
                #pragma unroll
                for (int tr = 0; tr < TROWS; tr++){
                    ffma2(acc[tr][0], nrp[tr][d], ea.x);
                    ffma2(acc[tr][1], nrp[tr][d], ea.y);
                    ffma2(acc[tr][2], nrp[tr][d], eb.x);
                    ffma2(acc[tr][3], nrp[tr][d], eb.y);
                }
            }
            #pragma unroll
            for (int tr = 0; tr < TROWS; tr++){
                float s[8] = {lo2(acc[tr][0]),hi2(acc[tr][0]),lo2(acc[tr][1]),hi2(acc[tr][1]),
                              lo2(acc[tr][2]),hi2(acc[tr][2]),lo2(acc[tr][3]),hi2(acc[tr][3])};
                #pragma unroll
                for (int k = 0; k < 8; k++){
                    int cc = cbase + tb + jj + k;
                    if (s[k] < best[tr]){ best[tr] = s[k]; bcode[tr] = cc; }
                }
            }
        }
    }
    #pragma unroll
    for (int tr = 0; tr < TROWS; tr++){
        if (act[tr]){
            unsigned long long key = ((unsigned long long)ford(best[tr]) << 32) | (unsigned)bcode[tr];
            atomicMin(&g_res64[base + row0 + tr*128], key);
        }
    }
}

// ---------------- separable staged gather (si<4) -> g_qup [b][y][x][c] ----------------
__global__ __launch_bounds__(256) void gather_sep_kernel(const float* __restrict__ emb,
        int si, int ph, int lph, int base){
    __shared__ int   s_code[64];
    __shared__ float s_q[64*17];          // [code][cl + pad]
    __shared__ float s_tmp[8*16*17];      // [py][x][cl + pad]
    int b = blockIdx.x, cg = blockIdx.y, t = threadIdx.x;
    int pp = ph*ph;

    if (t < pp) s_code[t] = (int)(g_res64[base + b*pp + t] & 0xFFFFFFFFull);
    __syncthreads();

    // stage q vectors: lanes vary cl -> coalesced emb reads
    for (int i = t; i < pp*16; i += 256){
        int cl = i & 15, code = i >> 4;
        s_q[code*17 + cl] = emb[s_code[code]*C + cg*16 + cl];
    }
    __syncthreads();

    // pass1: x-interp -> s_tmp[py][x][cl]
    int n1 = ph*256;
    for (int i = t; i < n1; i += 256){
        int cl = i & 15, x = (i >> 4) & 15, py = i >> 8;
        float acc = 0.f;
        #pragma unroll
        for (int ax = 0; ax < 4; ax++){
            int ix = g_itab[si][x][ax];
            acc += g_wtab[si][x][ax] * s_q[(py*ph + ix)*17 + cl];
        }
        s_tmp[(py*16 + x)*17 + cl] = acc;
    }
    __syncthreads();

    // pass2: y-interp -> g_qup[b][y][x][cg*16+cl] (coalesced)
    for (int i = t; i < 4096; i += 256){
        int cl = i & 15, x = (i >> 4) & 15, y = i >> 8;
        float acc = 0.f;
        #pragma unroll
        for (int ay = 0; ay < 4; ay++){
            int iy = g_itab[si][y][ay];
            acc += g_wtab[si][y][ay] * s_tmp[(iy*16 + x)*17 + cl];
        }
        g_qup[b*IMG + (y*16 + x)*32 + cg*16 + cl] = acc;
    }
}

// ---------------- direct gather (si=4): lanes vary c -> fully coalesced ----------------
__global__ void gather_direct_kernel(const float* __restrict__ emb, int base){
    int t = blockIdx.x*blockDim.x + threadIdx.x;
    if (t >= TOT) return;
    int c = t & 31, pix = (t >> 5) & 255, b = t >> 13;
    int code = (int)(g_res64[base + b*256 + pix] & 0xFFFFFFFFull);
    g_qup[t] = emb[code*C + c];   // g_qup [b][y][x][c]
}

// ---------------- Phi conv3x3, register-tiled 4oc x 4y per thread ----------------
// block 128 = x16 * yq4 * ocp2; grid (B, 4). s_w packed [ci][k][oc8] for LDS.128 weight loads.
__global__ __launch_bounds__(128) void conv_update_kernel(const float* __restrict__ z,
        const float* __restrict__ w, const float* __restrict__ bias, int si, float* __restrict__ out){
    __shared__ float s_in[C*257];       // [ci][y*16+x], pad 1 per ci
    __shared__ float s_w[C*9*8];        // [ci][ky*3+kx][oc_l]  (oc fastest for LDS.128)
    __shared__ float red[128];
    int b = blockIdx.x, og = blockIdx.y, t = threadIdx.x;

    // load q_up [pix][c] -> s_in[c][pix]  (conflict-free: bank = (c0+k) + pix mod 32)
    const float4* gsrc = (const float4*)(g_qup + b*IMG);
    for (int j = t; j < IMG/4; j += 128){
        float4 v = gsrc[j];
        int pix = j >> 3, c0 = (j & 7)*4;
        s_in[(c0+0)*257 + pix] = v.x;
        s_in[(c0+1)*257 + pix] = v.y;
        s_in[(c0+2)*257 + pix] = v.z;
        s_in[(c0+3)*257 + pix] = v.w;
    }
    // weights: global [oc_l][ci][k] -> smem [ci][k][oc_l]
    for (int i = t; i < 8*C*9; i += 128){
        int oc_l = i / (C*9);
        int rem  = i - oc_l*(C*9);
        s_w[rem*8 + oc_l] = w[og*8*C*9 + i];
    }
    __syncthreads();

    int x    = t & 15;        // lane dim -> conflict-free v loads
    int yq   = (t >> 4) & 3;  // rows 4yq..4yq+3
    int ocp  = t >> 6;        // 0..1 -> oc_l = ocp*4 .. +3
    int y0 = 4*yq;

    float acc[4][4];          // [oc][y]
    #pragma unroll
    for (int o = 0; o < 4; o++)
        #pragma unroll
        for (int i = 0; i < 4; i++) acc[o][i] = 0.f;

    for (int ci = 0; ci < C; ci++){
        const float* base_ci = s_in + ci*257;
        const float* wci = s_w + ci*9*8 + ocp*4;
        #pragma unroll
        for (int kx = 0; kx < 3; kx++){
            int xx = x + kx - 1;
            if (xx < 0 || xx >= HW) continue;   // zero pad
            // v[j] = in(y0 - 1 + j), j = 0..5
            float v[6];
            v[0] = (y0 >= 1)     ? base_ci[(y0-1)*16 + xx] : 0.f;
            v[1] = base_ci[(y0+0)*16 + xx];
            v[2] = base_ci[(y0+1)*16 + xx];
            v[3] = base_ci[(y0+2)*16 + xx];
            v[4] = base_ci[(y0+3)*16 + xx];
            v[5] = (y0 + 4 < HW) ? base_ci[(y0+4)*16 + xx] : 0.f;
            #pragma unroll
            for (int ky = 0; ky < 3; ky++){
                float4 w4 = *(const float4*)(wci + (ky*3 + kx)*8);   // 4 ocs, broadcast
                #pragma unroll
                for (int i = 0; i < 4; i++){
                    float vv = v[i + ky];
                    acc[0][i] += w4.x * vv;
                    acc[1][i] += w4.y * vv;
                    acc[2][i] += w4.z * vv;
                    acc[3][i] += w4.w * vv;
                }
            }
        }
    }

    float ls = 0.f;
    #pragma unroll
    for (int o = 0; o < 4; o++){
        int oc = og*8 + ocp*4 + o;
        float bval = bias[oc];
        int gbase = ((b*C + oc)*HW)*HW + x;
        #pragma unroll
        for (int i = 0; i < 4; i++){
            int y = y0 + i;
            float qv = 0.5f*s_in[oc*257 + y*16 + x] + 0.5f*(acc[o][i] + bval);
            int g = gbase + y*HW;
            float zr = g_zres[g] - qv;
            if (si < 4){
                g_zres[g] = zr;
            } else {
                out[g] = z[g] - zr;   // z_hat (straight-through value)
            }
            ls += zr*zr;              // (z_hat - z)^2 == zres_new^2
        }
    }
    red[t] = ls;
    __syncthreads();
    for (int s = 64; s > 0; s >>= 1){
        if (t < s) red[t] += red[t+s];
        __syncthreads();
    }
    if (t == 0) g_losspart[si*256 + b*4 + og] = red[0];
}

// ---------------- final pack: loss (parallel reduce) + idx floats ----------------
__global__ void pack_kernel(float* __restrict__ out){
    int t = blockIdx.x*blockDim.x + threadIdx.x;
    if (blockIdx.x == 0){
        __shared__ float red[256];
        float s = 0.f;
        for (int i = threadIdx.x; i < 5*256; i += 256) s += g_losspart[i];
        red[threadIdx.x] = s;
        __syncthreads();
        for (int k = 128; k > 0; k >>= 1){
            if (threadIdx.x < k) red[threadIdx.x] += red[threadIdx.x + k];
            __syncthreads();
        }
        if (threadIdx.x == 0) out[TOT] = red[0] * (1.25f / ((float)TOT * 5.f));
    }
    if (t < NIDX){
        int base, pp, ofs_row;
        if      (t <   64){ base=0;    pp=1;   ofs_row=0;  }
        else if (t <  320){ base=64;   pp=4;   ofs_row=1;  }
        else if (t < 1344){ base=320;  pp=16;  ofs_row=5;  }
        else if (t < 5440){ base=1344; pp=64;  ofs_row=21; }
        else              { base=5440; pp=256; ofs_row=85; }
        int r = t - base;
        int bb = r / pp, p = r % pp;
        int code = (int)(g_res64[t] & 0xFFFFFFFFull);
        out[TOT + 1 + bb*ROWLEN + ofs_row + p] = (float)code;
    }
}

extern "C" void kernel_launch(void* const* d_in, const int* in_sizes, int n_in,
                              void* d_out, int out_size){
    // Bind inputs by element count: z=524288, emb=131072, phi_w=36864, phi_b=128 (all distinct).
    const float* z = 0; const float* emb = 0; const float* phi_w = 0; const float* phi_b = 0;
    for (int i = 0; i < n_in; i++){
        switch (in_sizes[i]){
            case 524288: z     = (const float*)d_in[i]; break;
            case 131072: emb   = (const float*)d_in[i]; break;
            case 36864:  phi_w = (const float*)d_in[i]; break;
            case 128:    phi_b = (const float*)d_in[i]; break;
            default: break;
        }
    }
    float* out = (float*)d_out;
    (void)out_size;

    setup_kernel<<<(TOT + 255)/256, 256>>>(z, emb);

    // numpy-exact Phi tick selection (float64 linspace semantics, first-wins argmin)
    double start = 1.0/12.0;
    double stop  = 1.0 - 1.0/12.0;
    double step  = (stop - start) / 3.0;
    double ticks[4];
    for (int i = 0; i < 4; i++) ticks[i] = (double)i * step + start;
    ticks[3] = stop;
    int pis[5];
    for (int si = 0; si < 5; si++){
        double target = (double)si / 4.0;
        int bestp = 0; double bestd = fabs(ticks[0] - target);
        for (int p = 1; p < 4; p++){
            double d = fabs(ticks[p] - target);
            if (d < bestd){ bestd = d; bestp = p; }
        }
        pis[si] = bestp;
    }

    const int scales[5] = {1, 2, 4, 8, 16};
    const int iofs[5]   = {0, 64, 320, 1344, 5440};
    const int splits[5] = {32, 32, 16, 16, 8};
    const int fmodes[5] = {0, 0, 3, 2, 1};

    for (int si = 0; si < 5; si++){
        int ph = scales[si];
        int N  = B*ph*ph;
        if (si == 1) pool_kernel<<<(N*C + 255)/256, 256>>>(ph);
        int chunk = NE/splits[si];
        if (si >= 3){
            dim3 g((N + 255)/256, splits[si]);
            argmin_kernel<2><<<g, 128>>>(emb, N, chunk, iofs[si], fmodes[si]);
        } else {
            dim3 g((N + 127)/128, splits[si]);
            argmin_kernel<1><<<g, 128>>>(emb, N, chunk, iofs[si], fmodes[si]);
        }
        if (si < 4)
            gather_sep_kernel<<<dim3(B, 2), 256>>>(emb, si, ph, si, iofs[si]);
        else
            gather_direct_kernel<<<(TOT + 255)/256, 256>>>(emb, iofs[si]);
        conv_update_kernel<<<dim3(B, 4), 128>>>(z, phi_w + pis[si]*C*C*9, phi_b + pis[si]*C,
                                                si, (si == 4) ? out : (float*)0);
    }
    pack_kernel<<<(NIDX + 255)/256, 256>>>(out);
}

// round 13
// speedup vs baseline: 2.1440x; 1.0321x over previous
#include <cuda_runtime.h>
#include <cmath>

#define B 64
#define C 32
#define HW 16
#define IMG (C*HW*HW)        // 8192
#define TOT (B*IMG)          // 524288
#define NE 4096
#define NIDX 21824
#define ROWLEN 341
#define TCODES 128

// ---------------- scratch (no allocations allowed) ----------------
__device__ float g_zres[TOT];
__device__ float g_r[TOT];            // only scales 0..1 use this
__device__ float g_qup[TOT];          // layout [b][y][x][c] (channel-last)
__device__ float g_hesq[NE];          // 0.5*||e||^2
__device__ unsigned long long g_res64[NIDX];
__device__ float g_losspart[5*256];
__device__ int   g_itab[4][16][4];
__device__ float g_wtab[4][16][4];

// ---------------- helpers ----------------
__device__ __forceinline__ float cubicw(float x){
    const float A = -0.75f;
    x = fabsf(x);
    if (x <= 1.f) return ((A + 2.f)*x - (A + 3.f))*x*x + 1.f;
    if (x < 2.f)  return A*(((x - 5.f)*x + 8.f)*x - 4.f);
    return 0.f;
}
__device__ __forceinline__ void ffma2(unsigned long long &d, unsigned long long a, unsigned long long b){
    asm("fma.rn.f32x2 %0, %1, %2, %0;" : "+l"(d) : "l"(a), "l"(b));
}
__device__ __forceinline__ unsigned long long pk2(float a, float b){
    return ((unsigned long long)__float_as_uint(b) << 32) | (unsigned long long)__float_as_uint(a);
}
__device__ __forceinline__ float lo2(unsigned long long v){ return __uint_as_float((unsigned)v); }
__device__ __forceinline__ float hi2(unsigned long long v){ return __uint_as_float((unsigned)(v >> 32)); }
__device__ __forceinline__ unsigned ford(float f){
    unsigned u = __float_as_uint(f);
    return (u & 0x80000000u) ? ~u : (u | 0x80000000u);
}

// pooled residual row loader. fmode: 0 = g_r, 1 = f=1, 2 = f=2, 3 = f=4
__device__ __forceinline__ void load_r(int row, int fmode, float* r){
    if (fmode == 1){
        int bb = row >> 8, rem = row & 255;
        const float* p = g_zres + bb*IMG + rem;
        #pragma unroll
        for (int c = 0; c < C; c++) r[c] = p[c*256];
    } else if (fmode == 2){
        int bb = row >> 6, rem = row & 63;
        int y = rem >> 3, x = rem & 7;
        const float* p = g_zres + bb*IMG + (2*y)*16 + 2*x;
        #pragma unroll
        for (int c = 0; c < C; c++){
            const float* q = p + c*256;
            r[c] = (q[0] + q[1] + q[16] + q[17]) * 0.25f;
        }
    } else if (fmode == 3){
        int bb = row >> 4, rem = row & 15;
        int y = rem >> 2, x = rem & 3;
        const float* p = g_zres + bb*IMG + (4*y)*16 + 4*x;
        #pragma unroll
        for (int c = 0; c < C; c++){
            const float* q = p + c*256;
            float s = 0.f;
            #pragma unroll
            for (int dy = 0; dy < 4; dy++){
                s += q[dy*16 + 0]; s += q[dy*16 + 1]; s += q[dy*16 + 2]; s += q[dy*16 + 3];
            }
            r[c] = s * 0.0625f;
        }
    } else {
        const float4* rp = (const float4*)(g_r + row*C);
        #pragma unroll
        for (int k = 0; k < 8; k++){
            float4 v = rp[k];
            r[4*k+0] = v.x; r[4*k+1] = v.y; r[4*k+2] = v.z; r[4*k+3] = v.w;
        }
    }
}

// ---------------- setup (also pools scale 0, whose input is raw z) ----------------
__global__ void setup_kernel(const float* __restrict__ z, const float* __restrict__ emb){
    int t = blockIdx.x*blockDim.x + threadIdx.x;
    if (t < TOT) g_zres[t] = z[t];
    if (t < NIDX) g_res64[t] = 0xFFFFFFFFFFFFFFFFull;
    if (t < NE){
        float s = 0.f;
        #pragma unroll
        for (int k = 0; k < C; k++){ float e = emb[t*C + k]; s += e*e; }
        g_hesq[t] = 0.5f*s;
    }
    if (t < 2048){   // pool scale 0 (f=16): r[b][c] = mean z[b][c][:][:]
        int b = t >> 5, c = t & 31;
        const float4* p = (const float4*)(z + (b*C + c)*256);
        float s = 0.f;
        for (int k = 0; k < 64; k++){
            float4 v = p[k];
            s += v.x + v.y + v.z + v.w;
        }
        g_r[(b)*C + c] = s * (1.f/256.f);
    }
    if (t < 256){
        int s = t >> 6, rem = t & 63, Y = rem >> 2, a = rem & 3;
        int ph = 1 << s;
        float scale = (float)ph / 16.f;
        float src = ((float)Y + 0.5f)*scale - 0.5f;
        float i0 = floorf(src);
        float fr = src - i0;
        int off = a - 1;
        int idx = (int)i0 + off;
        idx = min(max(idx, 0), ph - 1);
        g_itab[s][Y][a] = idx;
        g_wtab[s][Y][a] = cubicw(fr - (float)off);
    }
}

// ---------------- area pool to [N][C] channel-last (scale 1 only) ----------------
__global__ void pool_kernel(int ph){
    int t = blockIdx.x*blockDim.x + threadIdx.x;
    int N = B*ph*ph;
    if (t >= N*C) return;
    int n = t >> 5, c = t & 31;
    int pp = ph*ph;
    int b = n / pp, rem = n % pp, y = rem / ph, x = rem % ph;
    int f = HW / ph;
    const float* base = g_zres + ((b*C + c)*HW + y*f)*HW + x*f;
    float s = 0.f;
    for (int dy = 0; dy < f; dy++)
        for (int dx = 0; dx < f; dx++)
            s += base[dy*HW + dx];
    g_r[n*C + c] = s * (1.f / (float)(f*f));
}

// ---------------- code search: score = 0.5||e||^2 - r.e, FFMA2, TROWS rows/thread ----------------
template<int TROWS>
__global__ __launch_bounds__(128) void argmin_kernel(const float* __restrict__ emb, int N, int chunk,
                                                     int base, int fmode){
    __shared__ __align__(16) float et[C*TCODES];   // transposed [dim][code]
    __shared__ __align__(16) float hs[TCODES];
    int tid = threadIdx.x;
    int row0 = blockIdx.x*(128*TROWS) + tid;
    int cbase = blockIdx.y * chunk;

    unsigned long long nrp[TROWS][C];    // packed {-r_d, -r_d}
    bool act[TROWS];
    #pragma unroll
    for (int tr = 0; tr < TROWS; tr++){
        int row = row0 + tr*128;
        act[tr] = row < N;
        if (act[tr]){
            float r[C];
            load_r(row, fmode, r);
            #pragma unroll
            for (int c = 0; c < C; c++) nrp[tr][c] = pk2(-r[c], -r[c]);
        }
    }
    float best[TROWS]; int bcode[TROWS];
    #pragma unroll
    for (int tr = 0; tr < TROWS; tr++){ best[tr] = 3.4e38f; bcode[tr] = 0; }

    for (int tb = 0; tb < chunk; tb += TCODES){
        int code = cbase + tb + tid;
        const float4* src = (const float4*)(emb + code*C);
        __syncthreads();   // prior tile fully consumed
        #pragma unroll
        for (int k = 0; k < 8; k++){
            float4 v = src[k];
            et[(4*k+0)*TCODES + tid] = v.x;
            et[(4*k+1)*TCODES + tid] = v.y;
            et[(4*k+2)*TCODES + tid] = v.z;
            et[(4*k+3)*TCODES + tid] = v.w;
        }
        hs[tid] = g_hesq[code];
        __syncthreads();

        for (int jj = 0; jj < TCODES; jj += 8){
            const ulonglong2* h2 = (const ulonglong2*)(hs + jj);
            ulonglong2 ha = h2[0], hb = h2[1];
            unsigned long long acc[TROWS][4];
            #pragma unroll
            for (int tr = 0; tr < TROWS; tr++){
                acc[tr][0] = ha.x; acc[tr][1] = ha.y; acc[tr][2] = hb.x; acc[tr][3] = hb.y;
            }
            #pragma unroll
            for (int d = 0; d < C; d++){
                const ulonglong2* e2 = (const ulonglong2*)(et + d*TCODES + jj);
                ulonglong2 ea = e2[0], eb = e2[1];
                #pragma unroll
                for (int tr = 0; tr < TROWS; tr++){
                    ffma2(acc[tr][0], nrp[tr][d], ea.x);
                    ffma2(acc[tr][1], nrp[tr][d], ea.y);
                    ffma2(acc[tr][2], nrp[tr][d], eb.x);
                    ffma2(acc[tr][3], nrp[tr][d], eb.y);
                }
            }
            #pragma unroll
            for (int tr = 0; tr < TROWS; tr++){
                float s[8] = {lo2(acc[tr][0]),hi2(acc[tr][0]),lo2(acc[tr][1]),hi2(acc[tr][1]),
                              lo2(acc[tr][2]),hi2(acc[tr][2]),lo2(acc[tr][3]),hi2(acc[tr][3])};
                #pragma unroll
                for (int k = 0; k < 8; k++){
                    int cc = cbase + tb + jj + k;
                    if (s[k] < best[tr]){ best[tr] = s[k]; bcode[tr] = cc; }
                }
            }
        }
    }
    #pragma unroll
    for (int tr = 0; tr < TROWS; tr++){
        if (act[tr]){
            unsigned long long key = ((unsigned long long)ford(best[tr]) << 32) | (unsigned)bcode[tr];
            atomicMin(&g_res64[base + row0 + tr*128], key);
        }
    }
}

// ---------------- separable staged gather (si<4) -> g_qup [b][y][x][c] ----------------
__global__ __launch_bounds__(256) void gather_sep_kernel(const float* __restrict__ emb,
        int si, int ph, int lph, int base){
    __shared__ int   s_code[64];
    __shared__ float s_q[64*17];          // [code][cl + pad]
    __shared__ float s_tmp[8*16*17];      // [py][x][cl + pad]
    int b = blockIdx.x, cg = blockIdx.y, t = threadIdx.x;
    int pp = ph*ph;

    if (t < pp) s_code[t] = (int)(g_res64[base + b*pp + t] & 0xFFFFFFFFull);
    __syncthreads();

    // stage q vectors: lanes vary cl -> coalesced emb reads
    for (int i = t; i < pp*16; i += 256){
        int cl = i & 15, code = i >> 4;
        s_q[code*17 + cl] = emb[s_code[code]*C + cg*16 + cl];
    }
    __syncthreads();

    // pass1: x-interp -> s_tmp[py][x][cl]
    int n1 = ph*256;
    for (int i = t; i < n1; i += 256){
        int cl = i & 15, x = (i >> 4) & 15, py = i >> 8;
        float acc = 0.f;
        #pragma unroll
        for (int ax = 0; ax < 4; ax++){
            int ix = g_itab[si][x][ax];
            acc += g_wtab[si][x][ax] * s_q[(py*ph + ix)*17 + cl];
        }
        s_tmp[(py*16 + x)*17 + cl] = acc;
    }
    __syncthreads();

    // pass2: y-interp -> g_qup[b][y][x][cg*16+cl] (coalesced)
    for (int i = t; i < 4096; i += 256){
        int cl = i & 15, x = (i >> 4) & 15, y = i >> 8;
        float acc = 0.f;
        #pragma unroll
        for (int ay = 0; ay < 4; ay++){
            int iy = g_itab[si][y][ay];
            acc += g_wtab[si][y][ay] * s_tmp[(iy*16 + x)*17 + cl];
        }
        g_qup[b*IMG + (y*16 + x)*32 + cg*16 + cl] = acc;
    }
}

// ---------------- direct gather (si=4): lanes vary c -> fully coalesced ----------------
__global__ void gather_direct_kernel(const float* __restrict__ emb, int base){
    int t = blockIdx.x*blockDim.x + threadIdx.x;
    if (t >= TOT) return;
    int c = t & 31, pix = (t >> 5) & 255, b = t >> 13;
    int code = (int)(g_res64[base + b*256 + pix] & 0xFFFFFFFFull);
    g_qup[t] = emb[code*C + c];   // g_qup [b][y][x][c]
}

// ---------------- Phi conv3x3, register-tiled 2oc x 4y per thread, 256 threads ----------------
// block 256 = x16 * yq4 * ocp4; grid (B, 4). s_w packed [ci][k][oc8] for LDS.64 weight loads.
__global__ __launch_bounds__(256) void conv_update_kernel(const float* __restrict__ z,
        const float* __restrict__ w, const float* __restrict__ bias, int si, float* __restrict__ out){
    __shared__ float s_in[C*257];       // [ci][y*16+x], pad 1 per ci
    __shared__ float s_w[C*9*8];        // [ci][ky*3+kx][oc_l]  (oc fastest)
    __shared__ float red[256];
    int b = blockIdx.x, og = blockIdx.y, t = threadIdx.x;

    // load q_up [pix][c] -> s_in[c][pix]  (conflict-free: bank = (c0+k) + pix mod 32)
    const float4* gsrc = (const float4*)(g_qup + b*IMG);
    for (int j = t; j < IMG/4; j += 256){
        float4 v = gsrc[j];
        int pix = j >> 3, c0 = (j & 7)*4;
        s_in[(c0+0)*257 + pix] = v.x;
        s_in[(c0+1)*257 + pix] = v.y;
        s_in[(c0+2)*257 + pix] = v.z;
        s_in[(c0+3)*257 + pix] = v.w;
    }
    // weights: global [oc_l][ci][k] -> smem [ci][k][oc_l]
    for (int i = t; i < 8*C*9; i += 256){
        int oc_l = i / (C*9);
        int rem  = i - oc_l*(C*9);
        s_w[rem*8 + oc_l] = w[og*8*C*9 + i];
    }
    __syncthreads();

    int x    = t & 15;        // lane dim -> conflict-free v loads
    int yq   = (t >> 4) & 3;  // rows 4yq..4yq+3
    int ocp  = t >> 6;        // 0..3 -> oc_l = ocp*2, ocp*2+1
    int y0 = 4*yq;

    float acc[2][4];          // [oc][y]
    #pragma unroll
    for (int o = 0; o < 2; o++)
        #pragma unroll
        for (int i = 0; i < 4; i++) acc[o][i] = 0.f;

    for (int ci = 0; ci < C; ci++){
        const float* base_ci = s_in + ci*257;
        const float* wci = s_w + ci*9*8 + ocp*2;
        #pragma unroll
        for (int kx = 0; kx < 3; kx++){
            int xx = x + kx - 1;
            if (xx < 0 || xx >= HW) continue;   // zero pad
            float v[6];
            v[0] = (y0 >= 1)     ? base_ci[(y0-1)*16 + xx] : 0.f;
            v[1] = base_ci[(y0+0)*16 + xx];
            v[2] = base_ci[(y0+1)*16 + xx];
            v[3] = base_ci[(y0+2)*16 + xx];
            v[4] = base_ci[(y0+3)*16 + xx];
            v[5] = (y0 + 4 < HW) ? base_ci[(y0+4)*16 + xx] : 0.f;
            #pragma unroll
            for (int ky = 0; ky < 3; ky++){
                float2 w2 = *(const float2*)(wci + (ky*3 + kx)*8);   // 2 ocs, broadcast
                #pragma unroll
                for (int i = 0; i < 4; i++){
                    float vv = v[i + ky];
                    acc[0][i] += w2.x * vv;
                    acc[1][i] += w2.y * vv;
                }
            }
        }
    }

    float ls = 0.f;
    #pragma unroll
    for (int o = 0; o < 2; o++){
        int oc = og*8 + ocp*2 + o;
        float bval = bias[oc];
        int gbase = ((b*C + oc)*HW)*HW + x;
        #pragma unroll
        for (int i = 0; i < 4; i++){
            int y = y0 + i;
            float qv = 0.5f*s_in[oc*257 + y*16 + x] + 0.5f*(acc[o][i] + bval);
            int g = gbase + y*HW;
            float zr = g_zres[g] - qv;
            if (si < 4){
                g_zres[g] = zr;
            } else {
                out[g] = z[g] - zr;   // z_hat (straight-through value)
            }
            ls += zr*zr;              // (z_hat - z)^2 == zres_new^2
        }
    }
    red[t] = ls;
    __syncthreads();
    for (int s = 128; s > 0; s >>= 1){
        if (t < s) red[t] += red[t+s];
        __syncthreads();
    }
    if (t == 0) g_losspart[si*256 + b*4 + og] = red[0];
}

// ---------------- final pack: loss (parallel reduce) + idx floats ----------------
__global__ void pack_kernel(float* __restrict__ out){
    int t = blockIdx.x*blockDim.x + threadIdx.x;
    if (blockIdx.x == 0){
        __shared__ float red[256];
        float s = 0.f;
        for (int i = threadIdx.x; i < 5*256; i += 256) s += g_losspart[i];
        red[threadIdx.x] = s;
        __syncthreads();
        for (int k = 128; k > 0; k >>= 1){
            if (threadIdx.x < k) red[threadIdx.x] += red[threadIdx.x + k];
            __syncthreads();
        }
        if (threadIdx.x == 0) out[TOT] = red[0] * (1.25f / ((float)TOT * 5.f));
    }
    if (t < NIDX){
        int base, pp, ofs_row;
        if      (t <   64){ base=0;    pp=1;   ofs_row=0;  }
        else if (t <  320){ base=64;   pp=4;   ofs_row=1;  }
        else if (t < 1344){ base=320;  pp=16;  ofs_row=5;  }
        else if (t < 5440){ base=1344; pp=64;  ofs_row=21; }
        else              { base=5440; pp=256; ofs_row=85; }
        int r = t - base;
        int bb = r / pp, p = r % pp;
        int code = (int)(g_res64[t] & 0xFFFFFFFFull);
        out[TOT + 1 + bb*ROWLEN + ofs_row + p] = (float)code;
    }
}

extern "C" void kernel_launch(void* const* d_in, const int* in_sizes, int n_in,
                              void* d_out, int out_size){
    // Bind inputs by element count: z=524288, emb=131072, phi_w=36864, phi_b=128 (all distinct).
    const float* z = 0; const float* emb = 0; const float* phi_w = 0; const float* phi_b = 0;
    for (int i = 0; i < n_in; i++){
        switch (in_sizes[i]){
            case 524288: z     = (const float*)d_in[i]; break;
            case 131072: emb   = (const float*)d_in[i]; break;
            case 36864:  phi_w = (const float*)d_in[i]; break;
            case 128:    phi_b = (const float*)d_in[i]; break;
            default: break;
        }
    }
    float* out = (float*)d_out;
    (void)out_size;

    setup_kernel<<<(TOT + 255)/256, 256>>>(z, emb);

    // numpy-exact Phi tick selection (float64 linspace semantics, first-wins argmin)
    double start = 1.0/12.0;
    double stop  = 1.0 - 1.0/12.0;
    double step  = (stop - start) / 3.0;
    double ticks[4];
    for (int i = 0; i < 4; i++) ticks[i] = (double)i * step + start;
    ticks[3] = stop;
    int pis[5];
    for (int si = 0; si < 5; si++){
        double target = (double)si / 4.0;
        int bestp = 0; double bestd = fabs(ticks[0] - target);
        for (int p = 1; p < 4; p++){
            double d = fabs(ticks[p] - target);
            if (d < bestd){ bestd = d; bestp = p; }
        }
        pis[si] = bestp;
    }

    const int scales[5] = {1, 2, 4, 8, 16};
    const int iofs[5]   = {0, 64, 320, 1344, 5440};
    const int splits[5] = {32, 32, 16, 16, 8};
    const int fmodes[5] = {0, 0, 3, 2, 1};

    for (int si = 0; si < 5; si++){
        int ph = scales[si];
        int N  = B*ph*ph;
        if (si == 1) pool_kernel<<<(N*C + 255)/256, 256>>>(ph);
        int chunk = NE/splits[si];
        if (si >= 3){
            dim3 g((N + 255)/256, splits[si]);
            argmin_kernel<2><<<g, 128>>>(emb, N, chunk, iofs[si], fmodes[si]);
        } else {
            dim3 g((N + 127)/128, splits[si]);
            argmin_kernel<1><<<g, 128>>>(emb, N, chunk, iofs[si], fmodes[si]);
        }
        if (si < 4)
            gather_sep_kernel<<<dim3(B, 2), 256>>>(emb, si, ph, si, iofs[si]);
        else
            gather_direct_kernel<<<(TOT + 255)/256, 256>>>(emb, iofs[si]);
        conv_update_kernel<<<dim3(B, 4), 256>>>(z, phi_w + pis[si]*C*C*9, phi_b + pis[si]*C,
                                                si, (si == 4) ? out : (float*)0);
    }
    pack_kernel<<<(NIDX + 255)/256, 256>>>(out);
}